// round 4
// baseline (speedup 1.0000x reference)
#include <cuda_runtime.h>
#include <math.h>

#define BSZ 4
#define CH  128
#define HH  128
#define WW  128
#define HWP (HH*WW)

typedef unsigned long long u64;

// -------- packed f32x2 helpers (SASS FFMA2) --------
__device__ __forceinline__ void ffma2(u64 &d, u64 a, u64 b){
    asm("fma.rn.f32x2 %0, %1, %2, %0;" : "+l"(d) : "l"(a), "l"(b));
}
__device__ __forceinline__ u64 pack2(float x, float y){
    u64 r; asm("mov.b64 %0, {%1, %2};" : "=l"(r) : "f"(x), "f"(y)); return r;
}
__device__ __forceinline__ void unpack2(u64 p, float &lo, float &hi){
    asm("mov.b64 {%0, %1}, %2;" : "=f"(lo), "=f"(hi) : "l"(p));
}

// -------- scratch (static device memory; no allocations) --------
__device__ float g_r1 [(size_t)BSZ*CH*HWP];   // bn1 output
__device__ float g_d1 [(size_t)BSZ*CH*HWP];   // layer1 output (post-prelu)
__device__ float g_offm[(size_t)BSZ*27*HWP];  // ch 0..17 offsets, 18..26 mask
__device__ float g_wTd1[9*CH*CH*2];           // w1 transposed+duplicated [k][c][2*co+{0,1}]
__device__ float g_wTd2[9*CH*CH*2];           // w2 transposed+duplicated

// -------- prep: transpose + duplicate main conv weights to [k][c][co dup] --------
__global__ void prep_wt_kernel(const float* __restrict__ w1, const float* __restrict__ w2){
    int i = blockIdx.x*256 + threadIdx.x;
    const int N = 9*CH*CH*2;
    if (i >= 2*N) return;
    const float* w = (i < N) ? w1 : w2;
    float*       o = (i < N) ? g_wTd1 : g_wTd2;
    int j  = (i < N) ? i : i - N;
    int co = (j >> 1) & (CH-1);       // duplicated slot pairs
    int c  = (j >> 8) & (CH-1);
    int k  =  j >> 15;
    o[j] = w[(co*CH + c)*9 + k];
}

// -------- bn1 elementwise --------
__global__ void bn1_kernel(const float4* __restrict__ x,
                           const float* __restrict__ g, const float* __restrict__ b,
                           const float* __restrict__ m, const float* __restrict__ v){
    int i = blockIdx.x*256 + threadIdx.x;          // over BSZ*CH*HWP/4 float4s
    int c = (i >> 12) & (CH-1);
    float s  = g[c] * rsqrtf(v[c] + 1e-5f);
    float bb = b[c] - m[c]*s;
    float4 xv = x[i];
    float4 r;
    r.x = xv.x*s + bb; r.y = xv.y*s + bb; r.z = xv.z*s + bb; r.w = xv.w*s + bb;
    ((float4*)g_r1)[i] = r;
}

// -------- fused offset(18) + mask(9) 3x3 conv, pad 1, co split in halves --------
// grid: 256 blocks = BSZ * (HH/4) * 2 halves.  block: 256 thr, 2 px/thread.
__global__ void __launch_bounds__(256,2)
offmod_kernel(const float* __restrict__ src,
              const float* __restrict__ offw, const float* __restrict__ offb,
              const float* __restrict__ modw, const float* __restrict__ modb){
    extern __shared__ float sm[];
    float* wsm   = sm;              // [c*9+k][16] (co slots, padded) -> 1152*16 floats
    float* patch = sm + 1152*16;    // 6 x 130 floats

    int t    = threadIdx.x;
    int half = blockIdx.x & 1;
    int h0   = ((blockIdx.x >> 1) & 31) * 4;
    int b    = blockIdx.x >> 6;

    int coBase = half * 14;
    int nCo    = half ? 13 : 14;

    for (int i = t; i < 1152*16; i += 256){
        int r = i >> 4;
        int j = i & 15;
        int cg = coBase + j;
        float val = 0.f;
        if (j < nCo)
            val = (cg < 18) ? offw[cg*1152 + r] : modw[(cg-18)*1152 + r];
        wsm[i] = val;
    }

    int p0 = 2*t;
    int tr = p0 >> 7;               // tile row 0..3
    int tw = p0 & 127;              // even col

    u64 acc2[8][2];                 // [co pair 0..7][px 0..1]
#pragma unroll
    for (int p = 0; p < 8; p++){ acc2[p][0] = 0ull; acc2[p][1] = 0ull; }

    for (int c = 0; c < CH; c++){
        __syncthreads();
        const float* sp = src + ((size_t)(b*CH + c))*HWP;
        for (int i = t; i < 780; i += 256){
            int pr = i / 130; int pc = i - pr*130;
            int y  = h0 - 1 + pr;
            int xx = pc - 1;
            float vv = 0.f;
            if ((unsigned)y < HH && (unsigned)xx < WW) vv = sp[y*WW + xx];
            patch[i] = vv;
        }
        __syncthreads();
#pragma unroll
        for (int k = 0; k < 9; k++){
            int ky = k/3, kx = k - ky*3;
            float v0 = patch[(tr+ky)*130 + tw + kx];
            float v1 = patch[(tr+ky)*130 + tw + kx + 1];
            u64 v0d = pack2(v0, v0);
            u64 v1d = pack2(v1, v1);
            const ulonglong2* wr = (const ulonglong2*)(wsm + (c*9 + k)*16);
#pragma unroll
            for (int q = 0; q < 4; q++){
                ulonglong2 wq = wr[q];    // broadcast (same addr whole block)
                ffma2(acc2[2*q  ][0], wq.x, v0d);
                ffma2(acc2[2*q  ][1], wq.x, v1d);
                ffma2(acc2[2*q+1][0], wq.y, v0d);
                ffma2(acc2[2*q+1][1], wq.y, v1d);
            }
        }
    }

    int h = h0 + tr;
    size_t pbase = (size_t)h*WW + tw;
#pragma unroll
    for (int p = 0; p < 8; p++){
        float a0lo, a0hi, a1lo, a1hi;
        unpack2(acc2[p][0], a0lo, a0hi);
        unpack2(acc2[p][1], a1lo, a1hi);
#pragma unroll
        for (int e = 0; e < 2; e++){
            int j  = 2*p + e;
            if (j >= nCo) continue;
            int co = coBase + j;
            float a0 = e ? a0hi : a0lo;
            float a1 = e ? a1hi : a1lo;
            if (co < 18){
                float bb = offb[co];
                a0 += bb; a1 += bb;
            } else {
                float bb = modb[co-18];
                a0 = 2.f/(1.f + __expf(-(a0 + bb)));
                a1 = 2.f/(1.f + __expf(-(a1 + bb)));
            }
            float* op = g_offm + ((size_t)(b*27 + co))*HWP + pbase;
            *(float2*)op = make_float2(a0, a1);
        }
    }
}

// -------- deformable conv implicit GEMM (FFMA2, px-paired, R1 memory layout) --------
// grid: 1024 blocks = BSZ*HH*2 ; block 256 thr; tile = 64 px
// MODE 0: out = prelu(conv) -> g_d1  (p0 = alpha)
// MODE 1: out = bn2(conv) + x -> d_out (p0 = x, bn params used)
template<int MODE>
__global__ void __launch_bounds__(256)
deform_kernel(const float* __restrict__ src, const float* __restrict__ wTd,
              const float* __restrict__ p0,
              const float* __restrict__ bn_g, const float* __restrict__ bn_b,
              const float* __restrict__ bn_m, const float* __restrict__ bn_v,
              float* __restrict__ out){
    __shared__ float cols[CH*64];     // [c][px]  (plain, not duplicated)
    __shared__ float s_wt[64*4];
    __shared__ int   s_ad[64*4];

    int t   = threadIdx.x;
    int b   = blockIdx.x >> 8;
    int rem = blockIdx.x & 255;
    int h   = rem >> 1;
    int w0  = (rem & 1) << 6;

    int tx  = t & 15;
    int ty  = t >> 4;
    int ty4 = ty*4;
    int pxme = t & 63;

    u64 acc2[8][2];                   // [co][px pair]; lo/hi of pair j = px 4tx+2j, 4tx+2j+1
#pragma unroll
    for (int j = 0; j < 8; j++){ acc2[j][0] = 0ull; acc2[j][1] = 0ull; }

    const float* srcb  = src + (size_t)b*CH*HWP;
    const float* offb_ = g_offm + (size_t)b*27*HWP;

    for (int k = 0; k < 9; k++){
        __syncthreads();
        if (t < 64){
            int w = w0 + t;
            int p = h*WW + w;
            float oy = offb_[(2*k  )*HWP + p];
            float ox = offb_[(2*k+1)*HWP + p];
            float mv = offb_[(18+k )*HWP + p];
            int ky = k/3, kx = k - ky*3;
            float py  = (float)(h - 1 + ky) + oy;
            float pxf = (float)(w - 1 + kx) + ox;
            float y0f = floorf(py), x0f = floorf(pxf);
            float ay = py - y0f, ax = pxf - x0f;
            int y0 = (int)y0f, x0 = (int)x0f;
#pragma unroll
            for (int j = 0; j < 4; j++){
                int dy = j >> 1, dx = j & 1;
                int yi = y0 + dy, xi = x0 + dx;
                bool ok = ((unsigned)yi < HH) && ((unsigned)xi < WW);
                int yc = min(max(yi, 0), HH-1);
                int xc = min(max(xi, 0), WW-1);
                float wy = dy ? ay : 1.f - ay;
                float wx = dx ? ax : 1.f - ax;
                s_ad[t*4+j] = yc*WW + xc;
                s_wt[t*4+j] = ok ? wy*wx*mv : 0.f;
            }
        }
        __syncthreads();

        // sample cols[c][px] for this k (same as R1)
        int a0 = s_ad[pxme*4+0], a1 = s_ad[pxme*4+1], a2 = s_ad[pxme*4+2], a3 = s_ad[pxme*4+3];
        float f0 = s_wt[pxme*4+0], f1 = s_wt[pxme*4+1], f2 = s_wt[pxme*4+2], f3 = s_wt[pxme*4+3];
        int cstart = t >> 6;
#pragma unroll 8
        for (int s = 0; s < 32; s++){
            int c = cstart + s*4;
            const float* sp = srcb + (size_t)c*HWP;
            float v = f0*sp[a0] + f1*sp[a1] + f2*sp[a2] + f3*sp[a3];
            cols[c*64 + pxme] = v;
        }
        __syncthreads();

        // FFMA2 GEMM: acc2[co][j] += (w_co,w_co) * (v_px2j, v_px2j+1)
        // cols pairs: one LDS.128 per c (same addr pattern as R1, 2-way conflict max)
        // weights: duplicated in global, broadcast across tx lanes, L1-resident
        const ulonglong2* cc = (const ulonglong2*)cols;                  // [c*16 + tx]
        const ulonglong2* wd = (const ulonglong2*)(wTd + (size_t)k*CH*CH*2);
#pragma unroll 4
        for (int c = 0; c < CH; c++){
            ulonglong2 cv = cc[c*16 + tx];          // cv.x=(px0,px1) cv.y=(px2,px3)
            ulonglong2 wA = wd[c*64 + ty4    ];     // (co0,co0),(co1,co1)
            ulonglong2 wB = wd[c*64 + ty4 + 1];     // (co2,co2),(co3,co3)
            ulonglong2 wC = wd[c*64 + ty4 + 2];
            ulonglong2 wD = wd[c*64 + ty4 + 3];
            ffma2(acc2[0][0], wA.x, cv.x);  ffma2(acc2[0][1], wA.x, cv.y);
            ffma2(acc2[1][0], wA.y, cv.x);  ffma2(acc2[1][1], wA.y, cv.y);
            ffma2(acc2[2][0], wB.x, cv.x);  ffma2(acc2[2][1], wB.x, cv.y);
            ffma2(acc2[3][0], wB.y, cv.x);  ffma2(acc2[3][1], wB.y, cv.y);
            ffma2(acc2[4][0], wC.x, cv.x);  ffma2(acc2[4][1], wC.x, cv.y);
            ffma2(acc2[5][0], wC.y, cv.x);  ffma2(acc2[5][1], wC.y, cv.y);
            ffma2(acc2[6][0], wD.x, cv.x);  ffma2(acc2[6][1], wD.x, cv.y);
            ffma2(acc2[7][0], wD.y, cv.x);  ffma2(acc2[7][1], wD.y, cv.y);
        }
    }

    // epilogue
    int co0  = ty*8;
    int wcol = w0 + tx*4;
    size_t obase = ((size_t)b*CH)*HWP + (size_t)h*WW + wcol;
#pragma unroll
    for (int j = 0; j < 8; j++){
        int co = co0 + j;
        float a0, a1, a2, a3;
        unpack2(acc2[j][0], a0, a1);
        unpack2(acc2[j][1], a2, a3);
        if (MODE == 0){
            float al = p0[co];            // alpha
            float4 o;
            o.x = a0 > 0.f ? a0 : al*a0;
            o.y = a1 > 0.f ? a1 : al*a1;
            o.z = a2 > 0.f ? a2 : al*a2;
            o.w = a3 > 0.f ? a3 : al*a3;
            *(float4*)(out + obase + (size_t)co*HWP) = o;
        } else {
            float s  = bn_g[co] * rsqrtf(bn_v[co] + 1e-5f);
            float bb = bn_b[co] - bn_m[co]*s;
            float4 xv = *(const float4*)(p0 + obase + (size_t)co*HWP);  // shortcut x
            float4 o;
            o.x = a0*s + bb + xv.x;
            o.y = a1*s + bb + xv.y;
            o.z = a2*s + bb + xv.z;
            o.w = a3*s + bb + xv.w;
            *(float4*)(out + obase + (size_t)co*HWP) = o;
        }
    }
}

// -------- host launcher --------
extern "C" void kernel_launch(void* const* d_in, const int* in_sizes, int n_in,
                              void* d_out, int out_size){
    const float* x      = (const float*)d_in[0];
    const float* bn1_g  = (const float*)d_in[1];
    const float* bn1_b  = (const float*)d_in[2];
    const float* bn1_m  = (const float*)d_in[3];
    const float* bn1_v  = (const float*)d_in[4];
    const float* off1_w = (const float*)d_in[5];
    const float* off1_b = (const float*)d_in[6];
    const float* mod1_w = (const float*)d_in[7];
    const float* mod1_b = (const float*)d_in[8];
    const float* w1     = (const float*)d_in[9];
    const float* alpha  = (const float*)d_in[10];
    const float* off2_w = (const float*)d_in[11];
    const float* off2_b = (const float*)d_in[12];
    const float* mod2_w = (const float*)d_in[13];
    const float* mod2_b = (const float*)d_in[14];
    const float* w2     = (const float*)d_in[15];
    const float* bn2_g  = (const float*)d_in[16];
    const float* bn2_b  = (const float*)d_in[17];
    const float* bn2_m  = (const float*)d_in[18];
    const float* bn2_v  = (const float*)d_in[19];
    float* out = (float*)d_out;

    float *r1p, *d1p, *wt1p, *wt2p;
    cudaGetSymbolAddress((void**)&r1p,  g_r1);
    cudaGetSymbolAddress((void**)&d1p,  g_d1);
    cudaGetSymbolAddress((void**)&wt1p, g_wTd1);
    cudaGetSymbolAddress((void**)&wt2p, g_wTd2);

    const int OFFMOD_SMEM = (1152*16 + 780) * (int)sizeof(float);   // ~77 KB
    cudaFuncSetAttribute(offmod_kernel, cudaFuncAttributeMaxDynamicSharedMemorySize, OFFMOD_SMEM);

    // 1) weight transpose + duplication
    prep_wt_kernel<<<(4*9*CH*CH + 255)/256, 256>>>(w1, w2);
    // 2) bn1
    bn1_kernel<<<(BSZ*CH*HWP/4)/256, 256>>>((const float4*)x, bn1_g, bn1_b, bn1_m, bn1_v);
    // 3) offsets + mask for layer 1
    offmod_kernel<<<256, 256, OFFMOD_SMEM>>>(r1p, off1_w, off1_b, mod1_w, mod1_b);
    // 4) deform conv 1 (+prelu) -> d1
    deform_kernel<0><<<1024, 256>>>(r1p, wt1p, alpha, nullptr, nullptr, nullptr, nullptr, d1p);
    // 5) offsets + mask for layer 2
    offmod_kernel<<<256, 256, OFFMOD_SMEM>>>(d1p, off2_w, off2_b, mod2_w, mod2_b);
    // 6) deform conv 2 (+bn2 +shortcut) -> out
    deform_kernel<1><<<1024, 256>>>(d1p, wt2p, x, bn2_g, bn2_b, bn2_m, bn2_v, out);
}

// round 8
// speedup vs baseline: 2.0483x; 2.0483x over previous
#include <cuda_runtime.h>
#include <cuda_bf16.h>
#include <math.h>
#include <cstdint>

#define BSZ 4
#define CH  128
#define HH  128
#define WW  128
#define HWP (HH*WW)

typedef unsigned long long u64;
typedef uint32_t u32;

// ================= scratch (static device memory) =================
__device__ float g_r1 [(size_t)BSZ*CH*HWP];   // bn1 output
__device__ float g_d1 [(size_t)BSZ*CH*HWP];   // layer1 output
__device__ float g_offm[(size_t)BSZ*27*HWP];  // ch 0..17 offsets, 18..26 mask
// fragment-packed bf16 weights: [k][prec][mi 8][ki 8][lane 32] uint4
__device__ uint4 g_wF1[9*2*8*8*32];
__device__ uint4 g_wF2[9*2*8*8*32];

// ================= helpers =================
__device__ __forceinline__ u32 smem_to_u32(const void* p){
    u32 a; asm("{ .reg .u64 t; cvta.to.shared.u64 t, %1; cvt.u32.u64 %0, t; }" : "=r"(a) : "l"(p));
    return a;
}
__device__ __forceinline__ u32 pack_bf2(float a, float b){
    __nv_bfloat162 h = __floats2bfloat162_rn(a, b);   // .x=a (low), .y=b (high)
    return *(u32*)&h;
}
__device__ __forceinline__ void mma_bf16(float* d, const u32* a, u32 b0, u32 b1){
    asm volatile(
        "mma.sync.aligned.m16n8k16.row.col.f32.bf16.bf16.f32 "
        "{%0,%1,%2,%3}, {%4,%5,%6,%7}, {%8,%9}, {%0,%1,%2,%3};"
        : "+f"(d[0]), "+f"(d[1]), "+f"(d[2]), "+f"(d[3])
        : "r"(a[0]), "r"(a[1]), "r"(a[2]), "r"(a[3]), "r"(b0), "r"(b1));
}
// NOTE: non-trans. cols smem is px-major (already B^T), so plain ldmatrix yields
// the col-major B fragment directly; .trans double-transposes (R7 bug).
__device__ __forceinline__ void ldmx4(u32* r, u32 addr){
    asm volatile("ldmatrix.sync.aligned.m8n8.x4.shared.b16 {%0,%1,%2,%3}, [%4];"
        : "=r"(r[0]), "=r"(r[1]), "=r"(r[2]), "=r"(r[3]) : "r"(addr));
}

// ================= prep: weights -> mma fragment order, bf16 hi/lo =================
// i over 2 layers * 9 k * 2 prec * 8 mi * 8 ki * 32 lanes = 73728
__global__ void prep_wf_kernel(const float* __restrict__ w1, const float* __restrict__ w2){
    int i = blockIdx.x*256 + threadIdx.x;
    if (i >= 73728) return;
    int lane = i & 31;
    int ki   = (i>>5) & 7;
    int mi   = (i>>8) & 7;
    int prec = (i>>11) & 1;
    int rest = i >> 12;            // 0..17
    int k    = rest % 9;
    int layer= rest / 9;
    const float* w = layer ? w2 : w1;

    int r  = lane >> 2;
    int cp = (lane & 3)*2;
    int row0 = mi*16 + r;
    int col0 = ki*16 + cp;

    float v[4][2];
#pragma unroll
    for (int q = 0; q < 4; q++){
        int ro = row0 + ((q & 1) ? 8 : 0);
        int co_ = col0 + ((q >> 1) ? 8 : 0);
#pragma unroll
        for (int e = 0; e < 2; e++){
            float val = w[(ro*CH + (co_+e))*9 + k];
            if (prec){
                float hi = __bfloat162float(__float2bfloat16(val));
                val = val - hi;
            }
            v[q][e] = val;
        }
    }
    uint4 o;
    o.x = pack_bf2(v[0][0], v[0][1]);
    o.y = pack_bf2(v[1][0], v[1][1]);
    o.z = pack_bf2(v[2][0], v[2][1]);
    o.w = pack_bf2(v[3][0], v[3][1]);
    uint4* dst = layer ? g_wF2 : g_wF1;
    dst[(((k*2 + prec)*8 + mi)*8 + ki)*32 + lane] = o;
}

// ================= bn1 elementwise =================
__global__ void bn1_kernel(const float4* __restrict__ x,
                           const float* __restrict__ g, const float* __restrict__ b,
                           const float* __restrict__ m, const float* __restrict__ v){
    int i = blockIdx.x*256 + threadIdx.x;
    int c = (i >> 12) & (CH-1);
    float s  = g[c] * rsqrtf(v[c] + 1e-5f);
    float bb = b[c] - m[c]*s;
    float4 xv = x[i];
    float4 r;
    r.x = xv.x*s + bb; r.y = xv.y*s + bb; r.z = xv.z*s + bb; r.w = xv.w*s + bb;
    ((float4*)g_r1)[i] = r;
}

// ================= fused offset+mask conv (unchanged, passing version) ==========
__global__ void __launch_bounds__(256,2)
offmod_kernel(const float* __restrict__ src,
              const float* __restrict__ offw, const float* __restrict__ offb,
              const float* __restrict__ modw, const float* __restrict__ modb){
    extern __shared__ float sm[];
    float* wsm   = sm;              // [c*9+k][16]
    float* patch = sm + 1152*16;    // 6 x 130

    int t    = threadIdx.x;
    int half = blockIdx.x & 1;
    int h0   = ((blockIdx.x >> 1) & 31) * 4;
    int b    = blockIdx.x >> 6;

    int coBase = half * 14;
    int nCo    = half ? 13 : 14;

    for (int i = t; i < 1152*16; i += 256){
        int r = i >> 4;
        int j = i & 15;
        int cg = coBase + j;
        float val = 0.f;
        if (j < nCo)
            val = (cg < 18) ? offw[cg*1152 + r] : modw[(cg-18)*1152 + r];
        wsm[i] = val;
    }

    int p0 = 2*t;
    int tr = p0 >> 7;
    int tw = p0 & 127;

    float acc[16][2];
#pragma unroll
    for (int p = 0; p < 16; p++){ acc[p][0] = 0.f; acc[p][1] = 0.f; }

    for (int c = 0; c < CH; c++){
        __syncthreads();
        const float* sp = src + ((size_t)(b*CH + c))*HWP;
        for (int i = t; i < 780; i += 256){
            int pr = i / 130; int pc = i - pr*130;
            int y  = h0 - 1 + pr;
            int xx = pc - 1;
            float vv = 0.f;
            if ((unsigned)y < HH && (unsigned)xx < WW) vv = sp[y*WW + xx];
            patch[i] = vv;
        }
        __syncthreads();
#pragma unroll
        for (int k = 0; k < 9; k++){
            int ky = k/3, kx = k - ky*3;
            float v0 = patch[(tr+ky)*130 + tw + kx];
            float v1 = patch[(tr+ky)*130 + tw + kx + 1];
            const float4* wr = (const float4*)(wsm + (c*9 + k)*16);
#pragma unroll
            for (int q = 0; q < 4; q++){
                float4 wq = wr[q];    // broadcast
                acc[4*q  ][0] += wq.x*v0; acc[4*q  ][1] += wq.x*v1;
                acc[4*q+1][0] += wq.y*v0; acc[4*q+1][1] += wq.y*v1;
                acc[4*q+2][0] += wq.z*v0; acc[4*q+2][1] += wq.z*v1;
                acc[4*q+3][0] += wq.w*v0; acc[4*q+3][1] += wq.w*v1;
            }
        }
    }

    int h = h0 + tr;
    size_t pbase = (size_t)h*WW + tw;
#pragma unroll
    for (int j = 0; j < 14; j++){
        if (j >= nCo) continue;
        int co = coBase + j;
        float a0 = acc[j][0], a1 = acc[j][1];
        if (co < 18){
            float bb = offb[co];
            a0 += bb; a1 += bb;
        } else {
            float bb = modb[co-18];
            a0 = 2.f/(1.f + __expf(-(a0 + bb)));
            a1 = 2.f/(1.f + __expf(-(a1 + bb)));
        }
        float* op = g_offm + ((size_t)(b*27 + co))*HWP + pbase;
        *(float2*)op = make_float2(a0, a1);
    }
}

// ================= deformable conv via warp-level bf16x3 HMMA =================
// grid 1024 = b(4) * h(128) * 2 halves; block 256 (8 warps); tile 64px x 128co.
// warp w: co0 = (w>>1)*32, px0 = (w&1)*32; warp tile 32co x 32px.
// cols smem: [px 64][c 136 bf16] rows (272B stride, conflict-free ldmatrix).
#define ROWB 272

template<int MODE>
__global__ void __launch_bounds__(256,2)
deform_mma_kernel(const float* __restrict__ src, const uint4* __restrict__ wF,
                  const float* __restrict__ p0,
                  const float* __restrict__ bn_g, const float* __restrict__ bn_b,
                  const float* __restrict__ bn_m, const float* __restrict__ bn_v,
                  float* __restrict__ out){
    __shared__ __align__(16) char colsH[64*ROWB];
    __shared__ __align__(16) char colsL[64*ROWB];
    __shared__ int   s_ad[64*4];
    __shared__ float s_wt[64*4];

    int t = threadIdx.x, lane = t & 31, wid = t >> 5;
    int b = blockIdx.x >> 8, rem = blockIdx.x & 255;
    int h = rem >> 1, w0 = (rem & 1) << 6;

    int co0 = (wid >> 1)*32;
    int px0 = (wid & 1)*32;
    int miB = co0 >> 4;             // base m-tile (0,2,4,6)

    // ldmatrix lane addressing (non-trans): matrix i rows from lanes 8i..8i+7
    int sub  = lane & 7;
    int grp  = lane >> 3;
    int lrow = ((grp >> 1) << 3) + sub;      // 0..15
    int lcoff= (grp & 1) << 4;               // 0 or 16 bytes

    u32 cHb = smem_to_u32(colsH);
    u32 cLb = smem_to_u32(colsL);

    float acc[2][4][4];
#pragma unroll
    for (int m = 0; m < 2; m++)
#pragma unroll
        for (int n = 0; n < 4; n++)
#pragma unroll
            for (int e = 0; e < 4; e++) acc[m][n][e] = 0.f;

    const float* srcb = src + (size_t)b*CH*HWP;
    const float* offm = g_offm + (size_t)b*27*HWP;

    int pxs = t >> 2;               // sampling px 0..63
    int cq  = t & 3;                // channel quarter

    for (int k = 0; k < 9; k++){
        __syncthreads();            // cols readers of tap k-1 done
        if (t < 64){
            int w = w0 + t;
            int p = h*WW + w;
            float oy = offm[(2*k  )*HWP + p];
            float ox = offm[(2*k+1)*HWP + p];
            float mv = offm[(18+k )*HWP + p];
            int ky = k/3, kx = k - ky*3;
            float py  = (float)(h - 1 + ky) + oy;
            float pxf = (float)(w - 1 + kx) + ox;
            float y0f = floorf(py), x0f = floorf(pxf);
            float ay = py - y0f, ax = pxf - x0f;
            int y0 = (int)y0f, x0 = (int)x0f;
#pragma unroll
            for (int j = 0; j < 4; j++){
                int dy = j >> 1, dx = j & 1;
                int yi = y0 + dy, xi = x0 + dx;
                bool ok = ((unsigned)yi < HH) && ((unsigned)xi < WW);
                int yc = min(max(yi, 0), HH-1);
                int xc = min(max(xi, 0), WW-1);
                float wy = dy ? ay : 1.f - ay;
                float wx = dx ? ax : 1.f - ax;
                s_ad[t*4+j] = yc*WW + xc;
                s_wt[t*4+j] = ok ? wy*wx*mv : 0.f;
            }
        }
        __syncthreads();

        // sample 32 channels for px=pxs, convert to bf16 hi/lo, store to smem
        {
            int a0 = s_ad[pxs*4+0], a1 = s_ad[pxs*4+1], a2 = s_ad[pxs*4+2], a3 = s_ad[pxs*4+3];
            float f0 = s_wt[pxs*4+0], f1 = s_wt[pxs*4+1], f2 = s_wt[pxs*4+2], f3 = s_wt[pxs*4+3];
#pragma unroll
            for (int g = 0; g < 4; g++){
                int cg0 = cq*32 + g*8;
                float v[8];
#pragma unroll
                for (int e = 0; e < 8; e++){
                    const float* sp = srcb + (size_t)(cg0 + e)*HWP;
                    v[e] = f0*sp[a0] + f1*sp[a1] + f2*sp[a2] + f3*sp[a3];
                }
                uint4 hq, lq;
                u32* hp = (u32*)&hq; u32* lp = (u32*)&lq;
#pragma unroll
                for (int q = 0; q < 4; q++){
                    float v0 = v[2*q], v1 = v[2*q+1];
                    __nv_bfloat162 h2 = __floats2bfloat162_rn(v0, v1);
                    float2 hf = __bfloat1622float2(h2);
                    __nv_bfloat162 l2 = __floats2bfloat162_rn(v0 - hf.x, v1 - hf.y);
                    hp[q] = *(u32*)&h2;
                    lp[q] = *(u32*)&l2;
                }
                *(uint4*)(colsH + pxs*ROWB + cg0*2) = hq;
                *(uint4*)(colsL + pxs*ROWB + cg0*2) = lq;
            }
        }
        __syncthreads();

        // HMMA: 3-pass hi/lo over K=128 (8 k-steps)
        const uint4* wH = wF + (size_t)(k*2    )*64*32;
        const uint4* wL = wF + (size_t)(k*2 + 1)*64*32;
#pragma unroll
        for (int ki = 0; ki < 8; ki++){
            uint4 aH0 = wH[((miB  )*8 + ki)*32 + lane];
            uint4 aH1 = wH[((miB+1)*8 + ki)*32 + lane];
            uint4 aL0 = wL[((miB  )*8 + ki)*32 + lane];
            uint4 aL1 = wL[((miB+1)*8 + ki)*32 + lane];
            u32 adr0 = (u32)((px0 + lrow)*ROWB + ki*32 + lcoff);
            u32 adr1 = adr0 + 16*ROWB;
            u32 bh[8], bl[8];
            ldmx4(bh    , cHb + adr0);   // n-tiles 0,1
            ldmx4(bh + 4, cHb + adr1);   // n-tiles 2,3
            ldmx4(bl    , cLb + adr0);
            ldmx4(bl + 4, cLb + adr1);
#pragma unroll
            for (int n = 0; n < 4; n++){
                u32 b0h = bh[2*n], b1h = bh[2*n+1];
                u32 b0l = bl[2*n], b1l = bl[2*n+1];
                mma_bf16(acc[0][n], (const u32*)&aH0, b0h, b1h);
                mma_bf16(acc[1][n], (const u32*)&aH1, b0h, b1h);
                mma_bf16(acc[0][n], (const u32*)&aL0, b0h, b1h);
                mma_bf16(acc[1][n], (const u32*)&aL1, b0h, b1h);
                mma_bf16(acc[0][n], (const u32*)&aH0, b0l, b1l);
                mma_bf16(acc[1][n], (const u32*)&aH1, b0l, b1l);
            }
        }
    }

    // ================= epilogue =================
    int rfrag = lane >> 2;           // fragment row 0..7
    int cfrag = (lane & 3)*2;        // fragment col 0,2,4,6
#pragma unroll
    for (int m = 0; m < 2; m++){
        int coA = co0 + m*16 + rfrag;       // rows r and r+8
        int coB = coA + 8;
        float sA, bA, sB, bB;
        if (MODE == 0){
            sA = p0[coA]; sB = p0[coB];     // alpha
        } else {
            sA = bn_g[coA] * rsqrtf(bn_v[coA] + 1e-5f);
            bA = bn_b[coA] - bn_m[coA]*sA;
            sB = bn_g[coB] * rsqrtf(bn_v[coB] + 1e-5f);
            bB = bn_b[coB] - bn_m[coB]*sB;
        }
#pragma unroll
        for (int n = 0; n < 4; n++){
            int px = px0 + n*8 + cfrag;
            size_t baseA = ((size_t)(b*CH + coA))*HWP + (size_t)h*WW + w0 + px;
            size_t baseB = baseA + (size_t)8*HWP;
            float d0 = acc[m][n][0], d1 = acc[m][n][1];
            float d2 = acc[m][n][2], d3 = acc[m][n][3];
            if (MODE == 0){
                d0 = d0 > 0.f ? d0 : sA*d0;
                d1 = d1 > 0.f ? d1 : sA*d1;
                d2 = d2 > 0.f ? d2 : sB*d2;
                d3 = d3 > 0.f ? d3 : sB*d3;
                *(float2*)(out + baseA) = make_float2(d0, d1);
                *(float2*)(out + baseB) = make_float2(d2, d3);
            } else {
                float2 xA = *(const float2*)(p0 + baseA);
                float2 xB = *(const float2*)(p0 + baseB);
                *(float2*)(out + baseA) = make_float2(d0*sA + bA + xA.x, d1*sA + bA + xA.y);
                *(float2*)(out + baseB) = make_float2(d2*sB + bB + xB.x, d3*sB + bB + xB.y);
            }
        }
    }
}

// ================= host launcher =================
extern "C" void kernel_launch(void* const* d_in, const int* in_sizes, int n_in,
                              void* d_out, int out_size){
    const float* x      = (const float*)d_in[0];
    const float* bn1_g  = (const float*)d_in[1];
    const float* bn1_b  = (const float*)d_in[2];
    const float* bn1_m  = (const float*)d_in[3];
    const float* bn1_v  = (const float*)d_in[4];
    const float* off1_w = (const float*)d_in[5];
    const float* off1_b = (const float*)d_in[6];
    const float* mod1_w = (const float*)d_in[7];
    const float* mod1_b = (const float*)d_in[8];
    const float* w1     = (const float*)d_in[9];
    const float* alpha  = (const float*)d_in[10];
    const float* off2_w = (const float*)d_in[11];
    const float* off2_b = (const float*)d_in[12];
    const float* mod2_w = (const float*)d_in[13];
    const float* mod2_b = (const float*)d_in[14];
    const float* w2     = (const float*)d_in[15];
    const float* bn2_g  = (const float*)d_in[16];
    const float* bn2_b  = (const float*)d_in[17];
    const float* bn2_m  = (const float*)d_in[18];
    const float* bn2_v  = (const float*)d_in[19];
    float* out = (float*)d_out;

    float *r1p, *d1p;
    uint4 *wf1, *wf2;
    cudaGetSymbolAddress((void**)&r1p, g_r1);
    cudaGetSymbolAddress((void**)&d1p, g_d1);
    cudaGetSymbolAddress((void**)&wf1, g_wF1);
    cudaGetSymbolAddress((void**)&wf2, g_wF2);

    const int OFFMOD_SMEM = (1152*16 + 780) * (int)sizeof(float);   // ~77 KB
    cudaFuncSetAttribute(offmod_kernel, cudaFuncAttributeMaxDynamicSharedMemorySize, OFFMOD_SMEM);

    // 1) weight prep (fragment-packed bf16 hi/lo)
    prep_wf_kernel<<<(73728 + 255)/256, 256>>>(w1, w2);
    // 2) bn1
    bn1_kernel<<<(BSZ*CH*HWP/4)/256, 256>>>((const float4*)x, bn1_g, bn1_b, bn1_m, bn1_v);
    // 3) offsets + mask for layer 1
    offmod_kernel<<<256, 256, OFFMOD_SMEM>>>(r1p, off1_w, off1_b, mod1_w, mod1_b);
    // 4) deform conv 1 (+prelu) -> d1
    deform_mma_kernel<0><<<1024, 256>>>(r1p, wf1, alpha, nullptr, nullptr, nullptr, nullptr, d1p);
    // 5) offsets + mask for layer 2
    offmod_kernel<<<256, 256, OFFMOD_SMEM>>>(d1p, off2_w, off2_b, mod2_w, mod2_b);
    // 6) deform conv 2 (+bn2 +shortcut) -> out
    deform_mma_kernel<1><<<1024, 256>>>(d1p, wf2, x, bn2_g, bn2_b, bn2_m, bn2_v, out);
}

// round 10
// speedup vs baseline: 4.6210x; 2.2561x over previous
#include <cuda_runtime.h>
#include <cuda_bf16.h>
#include <math.h>
#include <cstdint>

#define BSZ 4
#define CH  128
#define HH  128
#define WW  128
#define HWP (HH*WW)

typedef unsigned long long u64;
typedef uint32_t u32;

// ================= scratch (static device memory) =================
__device__ float g_r1 [(size_t)BSZ*HWP*CH];   // bn1 output, NHWC [b][h][w][c]
__device__ float g_d1 [(size_t)BSZ*HWP*CH];   // layer1 output, NHWC
__device__ float g_offm[(size_t)BSZ*27*HWP];  // CHW planes: 0..17 offsets, 18..26 mask
// deform weights, fragment-packed bf16: [k][prec][mi 8][ki 8][lane 32] uint4
__device__ uint4 g_wF1[9*2*8*8*32];
__device__ uint4 g_wF2[9*2*8*8*32];
// offmod weights (27 rows padded to 32): [k][prec][mi 2][ki 8][lane 32] uint4
__device__ uint4 g_oF1[9*2*2*8*32];
__device__ uint4 g_oF2[9*2*2*8*32];

// ================= helpers =================
__device__ __forceinline__ u32 smem_to_u32(const void* p){
    u32 a; asm("{ .reg .u64 t; cvta.to.shared.u64 t, %1; cvt.u32.u64 %0, t; }" : "=r"(a) : "l"(p));
    return a;
}
__device__ __forceinline__ u32 pack_bf2(float a, float b){
    __nv_bfloat162 h = __floats2bfloat162_rn(a, b);
    return *(u32*)&h;
}
__device__ __forceinline__ void cvt_hilo(float x, float y, u32 &h, u32 &l){
    __nv_bfloat162 h2 = __floats2bfloat162_rn(x, y);
    float2 hf = __bfloat1622float2(h2);
    __nv_bfloat162 l2 = __floats2bfloat162_rn(x - hf.x, y - hf.y);
    h = *(u32*)&h2; l = *(u32*)&l2;
}
__device__ __forceinline__ void mma_bf16(float* d, const u32* a, u32 b0, u32 b1){
    asm volatile(
        "mma.sync.aligned.m16n8k16.row.col.f32.bf16.bf16.f32 "
        "{%0,%1,%2,%3}, {%4,%5,%6,%7}, {%8,%9}, {%0,%1,%2,%3};"
        : "+f"(d[0]), "+f"(d[1]), "+f"(d[2]), "+f"(d[3])
        : "r"(a[0]), "r"(a[1]), "r"(a[2]), "r"(a[3]), "r"(b0), "r"(b1));
}
// non-trans: cols smem is px-major (already B^T) -> direct col-major B fragment
__device__ __forceinline__ void ldmx4(u32* r, u32 addr){
    asm volatile("ldmatrix.sync.aligned.m8n8.x4.shared.b16 {%0,%1,%2,%3}, [%4];"
        : "=r"(r[0]), "=r"(r[1]), "=r"(r[2]), "=r"(r[3]) : "r"(addr));
}

// ================= prep: deform weights -> fragment order, bf16 hi/lo ==========
__global__ void prep_wf_kernel(const float* __restrict__ w1, const float* __restrict__ w2){
    int i = blockIdx.x*256 + threadIdx.x;
    if (i >= 73728) return;
    int lane = i & 31;
    int ki   = (i>>5) & 7;
    int mi   = (i>>8) & 7;
    int prec = (i>>11) & 1;
    int rest = i >> 12;            // 0..17
    int k    = rest % 9;
    int layer= rest / 9;
    const float* w = layer ? w2 : w1;

    int r  = lane >> 2;
    int cp = (lane & 3)*2;
    int row0 = mi*16 + r;
    int col0 = ki*16 + cp;

    float v[4][2];
#pragma unroll
    for (int q = 0; q < 4; q++){
        int ro = row0 + ((q & 1) ? 8 : 0);
        int co_ = col0 + ((q >> 1) ? 8 : 0);
#pragma unroll
        for (int e = 0; e < 2; e++){
            float val = w[(ro*CH + (co_+e))*9 + k];
            if (prec){
                float hi = __bfloat162float(__float2bfloat16(val));
                val = val - hi;
            }
            v[q][e] = val;
        }
    }
    uint4 o;
    o.x = pack_bf2(v[0][0], v[0][1]);
    o.y = pack_bf2(v[1][0], v[1][1]);
    o.z = pack_bf2(v[2][0], v[2][1]);
    o.w = pack_bf2(v[3][0], v[3][1]);
    uint4* dst = layer ? g_wF2 : g_wF1;
    dst[(((k*2 + prec)*8 + mi)*8 + ki)*32 + lane] = o;
}

// ================= prep: offmod weights (27 co pad 32) -> fragments ============
__global__ void prep_of_kernel(const float* __restrict__ o1w, const float* __restrict__ m1w,
                               const float* __restrict__ o2w, const float* __restrict__ m2w){
    int i = blockIdx.x*256 + threadIdx.x;
    if (i >= 18432) return;
    int lane = i & 31;
    int ki   = (i>>5) & 7;
    int mi   = (i>>8) & 1;
    int prec = (i>>9) & 1;
    int rest = i >> 10;            // 0..17
    int k    = rest % 9;
    int layer= rest / 9;
    const float* ow = layer ? o2w : o1w;
    const float* mw = layer ? m2w : m1w;

    int r  = lane >> 2;
    int cp = (lane & 3)*2;
    int row0 = mi*16 + r;
    int col0 = ki*16 + cp;

    float v[4][2];
#pragma unroll
    for (int q = 0; q < 4; q++){
        int ro = row0 + ((q & 1) ? 8 : 0);
        int c_ = col0 + ((q >> 1) ? 8 : 0);
#pragma unroll
        for (int e = 0; e < 2; e++){
            int c = c_ + e;
            float val = 0.f;
            if (ro < 18)      val = ow[(ro*CH + c)*9 + k];
            else if (ro < 27) val = mw[((ro-18)*CH + c)*9 + k];
            if (prec){
                float hi = __bfloat162float(__float2bfloat16(val));
                val = val - hi;
            }
            v[q][e] = val;
        }
    }
    uint4 o;
    o.x = pack_bf2(v[0][0], v[0][1]);
    o.y = pack_bf2(v[1][0], v[1][1]);
    o.z = pack_bf2(v[2][0], v[2][1]);
    o.w = pack_bf2(v[3][0], v[3][1]);
    uint4* dst = layer ? g_oF2 : g_oF1;
    dst[(((k*2 + prec)*2 + mi)*8 + ki)*32 + lane] = o;
}

// ================= bn1 + transpose to NHWC =================
// grid 8192 = b(4) x h(128) x cb(4) x wb(4); block 256 (tx 32, ty 8)
__global__ void bn1_nhwc_kernel(const float* __restrict__ x,
                                const float* __restrict__ g, const float* __restrict__ b_,
                                const float* __restrict__ m, const float* __restrict__ v){
    __shared__ float tile[32][33];
    int bid = blockIdx.x;
    int wb = bid & 3, cb = (bid >> 2) & 3, h = (bid >> 4) & 127, b = bid >> 11;
    int tx = threadIdx.x & 31, ty = threadIdx.x >> 5;
    int c0 = cb*32, w0 = wb*32;
#pragma unroll
    for (int i = 0; i < 4; i++){
        int c = c0 + ty + i*8;
        float s  = g[c] * rsqrtf(v[c] + 1e-5f);
        float bb = b_[c] - m[c]*s;
        float xv = x[((size_t)(b*CH + c))*HWP + h*WW + w0 + tx];
        tile[ty + i*8][tx] = xv*s + bb;
    }
    __syncthreads();
#pragma unroll
    for (int i = 0; i < 4; i++){
        int w = w0 + ty + i*8;
        g_r1[(((size_t)b*HWP) + h*WW + w)*CH + c0 + tx] = tile[tx][ty + i*8];
    }
}

#define ROWB 272

// ================= offmod via HMMA (regular conv, NHWC src) =================
// grid 1024 = b*h*2half; block 256 (8 warps). M=32(27), N=64px, K=128/tap x 9 taps.
__global__ void __launch_bounds__(256,2)
offmod_mma_kernel(const float* __restrict__ src, const uint4* __restrict__ oF,
                  const float* __restrict__ offb, const float* __restrict__ modb){
    __shared__ __align__(16) char colsH[64*ROWB];
    __shared__ __align__(16) char colsL[64*ROWB];

    int t = threadIdx.x, lane = t & 31, wid = t >> 5;
    int b = blockIdx.x >> 8, rem = blockIdx.x & 255;
    int h = rem >> 1, w0 = (rem & 1) << 6;

    int mi  = wid >> 2;            // 0..1
    int px0 = (wid & 3) * 16;

    int sub  = lane & 7;
    int grp  = lane >> 3;
    int lrow = ((grp >> 1) << 3) + sub;
    int lcoff= (grp & 1) << 4;

    u32 cHb = smem_to_u32(colsH);
    u32 cLb = smem_to_u32(colsL);

    float acc[2][4];
#pragma unroll
    for (int n = 0; n < 2; n++)
#pragma unroll
        for (int e = 0; e < 4; e++) acc[n][e] = 0.f;

    const float* srcb = src + (size_t)b*HWP*CH;

    for (int k = 0; k < 9; k++){
        int ky = k/3, kx = k - ky*3;
        int y  = h + ky - 1;
        bool vy = (unsigned)y < HH;
        __syncthreads();
        // build B tile: warp per px (8 px each), lane = 4 channels
#pragma unroll
        for (int it = 0; it < 8; it++){
            int px = wid + it*8;
            int x  = w0 + px + kx - 1;
            float4 q = make_float4(0.f,0.f,0.f,0.f);
            if (vy && (unsigned)x < WW)
                q = ((const float4*)(srcb + ((size_t)y*WW + x)*CH))[lane];
            u32 h0,l0,h1,l1;
            cvt_hilo(q.x, q.y, h0, l0);
            cvt_hilo(q.z, q.w, h1, l1);
            *(uint2*)(colsH + px*ROWB + lane*8) = make_uint2(h0, h1);
            *(uint2*)(colsL + px*ROWB + lane*8) = make_uint2(l0, l1);
        }
        __syncthreads();

        const uint4* wH = oF + (size_t)(((k*2    )*2 + mi)*8)*32;
        const uint4* wL = oF + (size_t)(((k*2 + 1)*2 + mi)*8)*32;
#pragma unroll
        for (int ki = 0; ki < 8; ki++){
            uint4 aH = wH[ki*32 + lane];
            uint4 aL = wL[ki*32 + lane];
            u32 adr = (u32)((px0 + lrow)*ROWB + ki*32 + lcoff);
            u32 bh[4], bl[4];
            ldmx4(bh, cHb + adr);
            ldmx4(bl, cLb + adr);
#pragma unroll
            for (int n = 0; n < 2; n++){
                mma_bf16(acc[n], (const u32*)&aH, bh[2*n], bh[2*n+1]);
                mma_bf16(acc[n], (const u32*)&aL, bh[2*n], bh[2*n+1]);
                mma_bf16(acc[n], (const u32*)&aH, bl[2*n], bl[2*n+1]);
            }
        }
    }

    // epilogue -> g_offm CHW planes
    int rfrag = lane >> 2;
    int cfrag = (lane & 3)*2;
    int coA = mi*16 + rfrag;
    int coB = coA + 8;
#pragma unroll
    for (int n = 0; n < 2; n++){
        int px = px0 + n*8 + cfrag;
        size_t pb = (size_t)h*WW + w0 + px;
#pragma unroll
        for (int half = 0; half < 2; half++){
            int co = half ? coB : coA;
            float d0 = half ? acc[n][2] : acc[n][0];
            float d1 = half ? acc[n][3] : acc[n][1];
            if (co < 18){
                float bb = offb[co];
                *(float2*)(g_offm + ((size_t)(b*27 + co))*HWP + pb) = make_float2(d0+bb, d1+bb);
            } else if (co < 27){
                float bb = modb[co-18];
                float a0 = 2.f/(1.f + __expf(-(d0 + bb)));
                float a1 = 2.f/(1.f + __expf(-(d1 + bb)));
                *(float2*)(g_offm + ((size_t)(b*27 + co))*HWP + pb) = make_float2(a0, a1);
            }
        }
    }
}

// ================= deformable conv via HMMA, NHWC gather =================
// grid 1024; block 256 (8 warps); tile 64px x 128co.
// MODE 0: out = prelu(conv) -> NHWC d1 (p0 = alpha)
// MODE 1: out = bn2(conv) + x -> CHW d_out (p0 = x CHW)
template<int MODE>
__global__ void __launch_bounds__(256,2)
deform_mma_kernel(const float* __restrict__ src, const uint4* __restrict__ wF,
                  const float* __restrict__ p0,
                  const float* __restrict__ bn_g, const float* __restrict__ bn_b,
                  const float* __restrict__ bn_m, const float* __restrict__ bn_v,
                  float* __restrict__ out){
    __shared__ __align__(16) char colsH[64*ROWB];
    __shared__ __align__(16) char colsL[64*ROWB];
    __shared__ int   s_ad[64*4];
    __shared__ float s_wt[64*4];

    int t = threadIdx.x, lane = t & 31, wid = t >> 5;
    int b = blockIdx.x >> 8, rem = blockIdx.x & 255;
    int h = rem >> 1, w0 = (rem & 1) << 6;

    int co0 = (wid >> 1)*32;
    int px0 = (wid & 1)*32;
    int miB = co0 >> 4;

    int sub  = lane & 7;
    int grp  = lane >> 3;
    int lrow = ((grp >> 1) << 3) + sub;
    int lcoff= (grp & 1) << 4;

    u32 cHb = smem_to_u32(colsH);
    u32 cLb = smem_to_u32(colsL);

    float acc[2][4][4];
#pragma unroll
    for (int m = 0; m < 2; m++)
#pragma unroll
        for (int n = 0; n < 4; n++)
#pragma unroll
            for (int e = 0; e < 4; e++) acc[m][n][e] = 0.f;

    const float* srcb = src + (size_t)b*HWP*CH;
    const float* offm = g_offm + (size_t)b*27*HWP;

    for (int k = 0; k < 9; k++){
        __syncthreads();            // readers of tap k-1 done
        if (t < 64){
            int w = w0 + t;
            int p = h*WW + w;
            float oy = offm[(2*k  )*HWP + p];
            float ox = offm[(2*k+1)*HWP + p];
            float mv = offm[(18+k )*HWP + p];
            int ky = k/3, kx = k - ky*3;
            float py  = (float)(h - 1 + ky) + oy;
            float pxf = (float)(w - 1 + kx) + ox;
            float y0f = floorf(py), x0f = floorf(pxf);
            float ay = py - y0f, ax = pxf - x0f;
            int y0 = (int)y0f, x0 = (int)x0f;
#pragma unroll
            for (int j = 0; j < 4; j++){
                int dy = j >> 1, dx = j & 1;
                int yi = y0 + dy, xi = x0 + dx;
                bool ok = ((unsigned)yi < HH) && ((unsigned)xi < WW);
                int yc = min(max(yi, 0), HH-1);
                int xc = min(max(xi, 0), WW-1);
                float wy = dy ? ay : 1.f - ay;
                float wx = dx ? ax : 1.f - ax;
                s_ad[t*4+j] = (yc*WW + xc)*CH;           // NHWC element offset
                s_wt[t*4+j] = ok ? wy*wx*mv : 0.f;
            }
        }
        __syncthreads();

        // gather: warp per px (8 px each), lane = 4 consecutive channels (LDG.128)
#pragma unroll
        for (int it = 0; it < 8; it++){
            int px = wid + it*8;
            int a0 = s_ad[px*4+0], a1 = s_ad[px*4+1], a2 = s_ad[px*4+2], a3 = s_ad[px*4+3];
            float f0 = s_wt[px*4+0], f1 = s_wt[px*4+1], f2 = s_wt[px*4+2], f3 = s_wt[px*4+3];
            float4 q0 = ((const float4*)(srcb + a0))[lane];
            float4 q1 = ((const float4*)(srcb + a1))[lane];
            float4 q2 = ((const float4*)(srcb + a2))[lane];
            float4 q3 = ((const float4*)(srcb + a3))[lane];
            float4 vv;
            vv.x = f0*q0.x + f1*q1.x + f2*q2.x + f3*q3.x;
            vv.y = f0*q0.y + f1*q1.y + f2*q2.y + f3*q3.y;
            vv.z = f0*q0.z + f1*q1.z + f2*q2.z + f3*q3.z;
            vv.w = f0*q0.w + f1*q1.w + f2*q2.w + f3*q3.w;
            u32 h0,l0,h1,l1;
            cvt_hilo(vv.x, vv.y, h0, l0);
            cvt_hilo(vv.z, vv.w, h1, l1);
            *(uint2*)(colsH + px*ROWB + lane*8) = make_uint2(h0, h1);
            *(uint2*)(colsL + px*ROWB + lane*8) = make_uint2(l0, l1);
        }
        __syncthreads();

        // HMMA: 3-pass hi/lo over K=128 (8 k-steps)
        const uint4* wH = wF + (size_t)(k*2    )*64*32;
        const uint4* wL = wF + (size_t)(k*2 + 1)*64*32;
#pragma unroll
        for (int ki = 0; ki < 8; ki++){
            uint4 aH0 = wH[((miB  )*8 + ki)*32 + lane];
            uint4 aH1 = wH[((miB+1)*8 + ki)*32 + lane];
            uint4 aL0 = wL[((miB  )*8 + ki)*32 + lane];
            uint4 aL1 = wL[((miB+1)*8 + ki)*32 + lane];
            u32 adr0 = (u32)((px0 + lrow)*ROWB + ki*32 + lcoff);
            u32 adr1 = adr0 + 16*ROWB;
            u32 bh[8], bl[8];
            ldmx4(bh    , cHb + adr0);
            ldmx4(bh + 4, cHb + adr1);
            ldmx4(bl    , cLb + adr0);
            ldmx4(bl + 4, cLb + adr1);
#pragma unroll
            for (int n = 0; n < 4; n++){
                u32 b0h = bh[2*n], b1h = bh[2*n+1];
                u32 b0l = bl[2*n], b1l = bl[2*n+1];
                mma_bf16(acc[0][n], (const u32*)&aH0, b0h, b1h);
                mma_bf16(acc[1][n], (const u32*)&aH1, b0h, b1h);
                mma_bf16(acc[0][n], (const u32*)&aL0, b0h, b1h);
                mma_bf16(acc[1][n], (const u32*)&aL1, b0h, b1h);
                mma_bf16(acc[0][n], (const u32*)&aH0, b0l, b1l);
                mma_bf16(acc[1][n], (const u32*)&aH1, b0l, b1l);
            }
        }
    }

    // ================= epilogue =================
    int rfrag = lane >> 2;
    int cfrag = (lane & 3)*2;
#pragma unroll
    for (int m = 0; m < 2; m++){
        int coA = co0 + m*16 + rfrag;
        int coB = coA + 8;
        if (MODE == 0){
            float aA = p0[coA], aB = p0[coB];    // alpha
#pragma unroll
            for (int n = 0; n < 4; n++){
                int px = px0 + n*8 + cfrag;
                size_t base = (((size_t)b*HWP) + h*WW + w0 + px)*CH;   // NHWC
                float d0 = acc[m][n][0], d1 = acc[m][n][1];
                float d2 = acc[m][n][2], d3 = acc[m][n][3];
                out[base + coA]      = d0 > 0.f ? d0 : aA*d0;
                out[base + CH + coA] = d1 > 0.f ? d1 : aA*d1;
                out[base + coB]      = d2 > 0.f ? d2 : aB*d2;
                out[base + CH + coB] = d3 > 0.f ? d3 : aB*d3;
            }
        } else {
            float sA  = bn_g[coA] * rsqrtf(bn_v[coA] + 1e-5f);
            float bA  = bn_b[coA] - bn_m[coA]*sA;
            float sB  = bn_g[coB] * rsqrtf(bn_v[coB] + 1e-5f);
            float bB  = bn_b[coB] - bn_m[coB]*sB;
#pragma unroll
            for (int n = 0; n < 4; n++){
                int px = px0 + n*8 + cfrag;
                size_t baseA = ((size_t)(b*CH + coA))*HWP + (size_t)h*WW + w0 + px;
                size_t baseB = baseA + (size_t)8*HWP;
                float2 xA = *(const float2*)(p0 + baseA);
                float2 xB = *(const float2*)(p0 + baseB);
                float d0 = acc[m][n][0], d1 = acc[m][n][1];
                float d2 = acc[m][n][2], d3 = acc[m][n][3];
                *(float2*)(out + baseA) = make_float2(d0*sA + bA + xA.x, d1*sA + bA + xA.y);
                *(float2*)(out + baseB) = make_float2(d2*sB + bB + xB.x, d3*sB + bB + xB.y);
            }
        }
    }
}

// ================= host launcher =================
extern "C" void kernel_launch(void* const* d_in, const int* in_sizes, int n_in,
                              void* d_out, int out_size){
    const float* x      = (const float*)d_in[0];
    const float* bn1_g  = (const float*)d_in[1];
    const float* bn1_b  = (const float*)d_in[2];
    const float* bn1_m  = (const float*)d_in[3];
    const float* bn1_v  = (const float*)d_in[4];
    const float* off1_w = (const float*)d_in[5];
    const float* off1_b = (const float*)d_in[6];
    const float* mod1_w = (const float*)d_in[7];
    const float* mod1_b = (const float*)d_in[8];
    const float* w1     = (const float*)d_in[9];
    const float* alpha  = (const float*)d_in[10];
    const float* off2_w = (const float*)d_in[11];
    const float* off2_b = (const float*)d_in[12];
    const float* mod2_w = (const float*)d_in[13];
    const float* mod2_b = (const float*)d_in[14];
    const float* w2     = (const float*)d_in[15];
    const float* bn2_g  = (const float*)d_in[16];
    const float* bn2_b  = (const float*)d_in[17];
    const float* bn2_m  = (const float*)d_in[18];
    const float* bn2_v  = (const float*)d_in[19];
    float* out = (float*)d_out;

    float *r1p, *d1p;
    uint4 *wf1, *wf2, *of1, *of2;
    cudaGetSymbolAddress((void**)&r1p, g_r1);
    cudaGetSymbolAddress((void**)&d1p, g_d1);
    cudaGetSymbolAddress((void**)&wf1, g_wF1);
    cudaGetSymbolAddress((void**)&wf2, g_wF2);
    cudaGetSymbolAddress((void**)&of1, g_oF1);
    cudaGetSymbolAddress((void**)&of2, g_oF2);

    // 1) weight prep
    prep_wf_kernel<<<(73728 + 255)/256, 256>>>(w1, w2);
    prep_of_kernel<<<(18432 + 255)/256, 256>>>(off1_w, mod1_w, off2_w, mod2_w);
    // 2) bn1 -> NHWC r1
    bn1_nhwc_kernel<<<8192, 256>>>(x, bn1_g, bn1_b, bn1_m, bn1_v);
    // 3) offsets + mask for layer 1 (HMMA)
    offmod_mma_kernel<<<1024, 256>>>(r1p, of1, off1_b, mod1_b);
    // 4) deform conv 1 (+prelu) -> NHWC d1
    deform_mma_kernel<0><<<1024, 256>>>(r1p, wf1, alpha, nullptr, nullptr, nullptr, nullptr, d1p);
    // 5) offsets + mask for layer 2 (HMMA)
    offmod_mma_kernel<<<1024, 256>>>(d1p, of2, off2_b, mod2_b);
    // 6) deform conv 2 (+bn2 +shortcut) -> CHW out
    deform_mma_kernel<1><<<1024, 256>>>(d1p, wf2, x, bn2_g, bn2_b, bn2_m, bn2_v, out);
}

// round 11
// speedup vs baseline: 4.8576x; 1.0512x over previous
#include <cuda_runtime.h>
#include <cuda_bf16.h>
#include <math.h>
#include <cstdint>

#define BSZ 4
#define CH  128
#define HH  128
#define WW  128
#define HWP (HH*WW)

typedef unsigned long long u64;
typedef uint32_t u32;

// ================= scratch (static device memory) =================
__device__ float g_r1 [(size_t)BSZ*HWP*CH];   // bn1 output, NHWC [b][h][w][c]
__device__ float g_d1 [(size_t)BSZ*HWP*CH];   // layer1 output, NHWC
__device__ float g_offm[(size_t)BSZ*27*HWP];  // CHW planes: 0..17 offsets, 18..26 mask
// deform weights, fragment-packed bf16: [k][prec][mi 8][ki 8][lane 32] uint4
__device__ uint4 g_wF1[9*2*8*8*32];
__device__ uint4 g_wF2[9*2*8*8*32];
// offmod weights (27 rows padded to 32): [k][prec][mi 2][ki 8][lane 32] uint4
__device__ uint4 g_oF1[9*2*2*8*32];
__device__ uint4 g_oF2[9*2*2*8*32];

// ================= helpers =================
__device__ __forceinline__ u32 smem_to_u32(const void* p){
    u32 a; asm("{ .reg .u64 t; cvta.to.shared.u64 t, %1; cvt.u32.u64 %0, t; }" : "=r"(a) : "l"(p));
    return a;
}
__device__ __forceinline__ u32 pack_bf2(float a, float b){
    __nv_bfloat162 h = __floats2bfloat162_rn(a, b);
    return *(u32*)&h;
}
__device__ __forceinline__ void cvt_hilo(float x, float y, u32 &h, u32 &l){
    __nv_bfloat162 h2 = __floats2bfloat162_rn(x, y);
    float2 hf = __bfloat1622float2(h2);
    __nv_bfloat162 l2 = __floats2bfloat162_rn(x - hf.x, y - hf.y);
    h = *(u32*)&h2; l = *(u32*)&l2;
}
__device__ __forceinline__ void mma_bf16(float* d, const u32* a, u32 b0, u32 b1){
    asm volatile(
        "mma.sync.aligned.m16n8k16.row.col.f32.bf16.bf16.f32 "
        "{%0,%1,%2,%3}, {%4,%5,%6,%7}, {%8,%9}, {%0,%1,%2,%3};"
        : "+f"(d[0]), "+f"(d[1]), "+f"(d[2]), "+f"(d[3])
        : "r"(a[0]), "r"(a[1]), "r"(a[2]), "r"(a[3]), "r"(b0), "r"(b1));
}
// non-trans: cols smem is px-major (already B^T) -> direct col-major B fragment
__device__ __forceinline__ void ldmx4(u32* r, u32 addr){
    asm volatile("ldmatrix.sync.aligned.m8n8.x4.shared.b16 {%0,%1,%2,%3}, [%4];"
        : "=r"(r[0]), "=r"(r[1]), "=r"(r[2]), "=r"(r[3]) : "r"(addr));
}

#define ROWB 272
#define BUFB (64*ROWB)        // 17408 bytes per precision tile
#define BUFP (2*BUFB)         // 34816 bytes per (H+L) buffer
#define PIPE_SMEM (2*BUFP)    // 69632 bytes double-buffered

// ================= prep: deform weights -> fragment order, bf16 hi/lo ==========
__global__ void prep_wf_kernel(const float* __restrict__ w1, const float* __restrict__ w2){
    int i = blockIdx.x*256 + threadIdx.x;
    if (i >= 73728) return;
    int lane = i & 31;
    int ki   = (i>>5) & 7;
    int mi   = (i>>8) & 7;
    int prec = (i>>11) & 1;
    int rest = i >> 12;            // 0..17
    int k    = rest % 9;
    int layer= rest / 9;
    const float* w = layer ? w2 : w1;

    int r  = lane >> 2;
    int cp = (lane & 3)*2;
    int row0 = mi*16 + r;
    int col0 = ki*16 + cp;

    float v[4][2];
#pragma unroll
    for (int q = 0; q < 4; q++){
        int ro = row0 + ((q & 1) ? 8 : 0);
        int co_ = col0 + ((q >> 1) ? 8 : 0);
#pragma unroll
        for (int e = 0; e < 2; e++){
            float val = w[(ro*CH + (co_+e))*9 + k];
            if (prec){
                float hi = __bfloat162float(__float2bfloat16(val));
                val = val - hi;
            }
            v[q][e] = val;
        }
    }
    uint4 o;
    o.x = pack_bf2(v[0][0], v[0][1]);
    o.y = pack_bf2(v[1][0], v[1][1]);
    o.z = pack_bf2(v[2][0], v[2][1]);
    o.w = pack_bf2(v[3][0], v[3][1]);
    uint4* dst = layer ? g_wF2 : g_wF1;
    dst[(((k*2 + prec)*8 + mi)*8 + ki)*32 + lane] = o;
}

// ================= prep: offmod weights (27 co pad 32) -> fragments ============
__global__ void prep_of_kernel(const float* __restrict__ o1w, const float* __restrict__ m1w,
                               const float* __restrict__ o2w, const float* __restrict__ m2w){
    int i = blockIdx.x*256 + threadIdx.x;
    if (i >= 18432) return;
    int lane = i & 31;
    int ki   = (i>>5) & 7;
    int mi   = (i>>8) & 1;
    int prec = (i>>9) & 1;
    int rest = i >> 10;            // 0..17
    int k    = rest % 9;
    int layer= rest / 9;
    const float* ow = layer ? o2w : o1w;
    const float* mw = layer ? m2w : m1w;

    int r  = lane >> 2;
    int cp = (lane & 3)*2;
    int row0 = mi*16 + r;
    int col0 = ki*16 + cp;

    float v[4][2];
#pragma unroll
    for (int q = 0; q < 4; q++){
        int ro = row0 + ((q & 1) ? 8 : 0);
        int c_ = col0 + ((q >> 1) ? 8 : 0);
#pragma unroll
        for (int e = 0; e < 2; e++){
            int c = c_ + e;
            float val = 0.f;
            if (ro < 18)      val = ow[(ro*CH + c)*9 + k];
            else if (ro < 27) val = mw[((ro-18)*CH + c)*9 + k];
            if (prec){
                float hi = __bfloat162float(__float2bfloat16(val));
                val = val - hi;
            }
            v[q][e] = val;
        }
    }
    uint4 o;
    o.x = pack_bf2(v[0][0], v[0][1]);
    o.y = pack_bf2(v[1][0], v[1][1]);
    o.z = pack_bf2(v[2][0], v[2][1]);
    o.w = pack_bf2(v[3][0], v[3][1]);
    uint4* dst = layer ? g_oF2 : g_oF1;
    dst[(((k*2 + prec)*2 + mi)*8 + ki)*32 + lane] = o;
}

// ================= bn1 + transpose to NHWC =================
__global__ void bn1_nhwc_kernel(const float* __restrict__ x,
                                const float* __restrict__ g, const float* __restrict__ b_,
                                const float* __restrict__ m, const float* __restrict__ v){
    __shared__ float tile[32][33];
    int bid = blockIdx.x;
    int wb = bid & 3, cb = (bid >> 2) & 3, h = (bid >> 4) & 127, b = bid >> 11;
    int tx = threadIdx.x & 31, ty = threadIdx.x >> 5;
    int c0 = cb*32, w0 = wb*32;
#pragma unroll
    for (int i = 0; i < 4; i++){
        int c = c0 + ty + i*8;
        float s  = g[c] * rsqrtf(v[c] + 1e-5f);
        float bb = b_[c] - m[c]*s;
        float xv = x[((size_t)(b*CH + c))*HWP + h*WW + w0 + tx];
        tile[ty + i*8][tx] = xv*s + bb;
    }
    __syncthreads();
#pragma unroll
    for (int i = 0; i < 4; i++){
        int w = w0 + ty + i*8;
        g_r1[(((size_t)b*HWP) + h*WW + w)*CH + c0 + tx] = tile[tx][ty + i*8];
    }
}

// ================= offmod via HMMA, pipelined (1 sync/tap) =================
// grid 1024 = b*h*2half; block 256 (8 warps). M=32(27), N=64px, K=128/tap x 9 taps.
__global__ void __launch_bounds__(256,2)
offmod_mma_kernel(const float* __restrict__ src, const uint4* __restrict__ oF,
                  const float* __restrict__ offb, const float* __restrict__ modb){
    extern __shared__ __align__(16) char dsm[];

    int t = threadIdx.x, lane = t & 31, wid = t >> 5;
    int b = blockIdx.x >> 8, rem = blockIdx.x & 255;
    int h = rem >> 1, w0 = (rem & 1) << 6;

    int mi  = wid >> 2;            // 0..1
    int px0 = (wid & 3) * 16;

    int sub  = lane & 7;
    int grp  = lane >> 3;
    int lrow = ((grp >> 1) << 3) + sub;
    int lcoff= (grp & 1) << 4;

    u32 smb = smem_to_u32(dsm);

    float acc[2][4];
#pragma unroll
    for (int n = 0; n < 2; n++)
#pragma unroll
        for (int e = 0; e < 4; e++) acc[n][e] = 0.f;

    const float* srcb = src + (size_t)b*HWP*CH;

    auto gatherO = [&](int k, int buf){
        int ky = k/3, kx = k - ky*3;
        int y  = h + ky - 1;
        bool vy = (unsigned)y < HH;
        char* cH = dsm + buf*BUFP;
        char* cL = cH + BUFB;
#pragma unroll
        for (int it = 0; it < 8; it++){
            int px = wid + it*8;
            int x  = w0 + px + kx - 1;
            float4 q = make_float4(0.f,0.f,0.f,0.f);
            if (vy && (unsigned)x < WW)
                q = ((const float4*)(srcb + ((size_t)y*WW + x)*CH))[lane];
            u32 h0,l0,h1,l1;
            cvt_hilo(q.x, q.y, h0, l0);
            cvt_hilo(q.z, q.w, h1, l1);
            *(uint2*)(cH + px*ROWB + lane*8) = make_uint2(h0, h1);
            *(uint2*)(cL + px*ROWB + lane*8) = make_uint2(l0, l1);
        }
    };

    gatherO(0, 0);

    for (int k = 0; k < 9; k++){
        __syncthreads();
        u32 cHb = smb + (k & 1)*BUFP;
        u32 cLb = cHb + BUFB;
        const uint4* wH = oF + (size_t)(((k*2    )*2 + mi)*8)*32;
        const uint4* wL = oF + (size_t)(((k*2 + 1)*2 + mi)*8)*32;
#pragma unroll
        for (int ki = 0; ki < 8; ki++){
            uint4 aH = wH[ki*32 + lane];
            uint4 aL = wL[ki*32 + lane];
            u32 adr = (u32)((px0 + lrow)*ROWB + ki*32 + lcoff);
            u32 bh[4], bl[4];
            ldmx4(bh, cHb + adr);
            ldmx4(bl, cLb + adr);
#pragma unroll
            for (int n = 0; n < 2; n++){
                mma_bf16(acc[n], (const u32*)&aH, bh[2*n], bh[2*n+1]);
                mma_bf16(acc[n], (const u32*)&aL, bh[2*n], bh[2*n+1]);
                mma_bf16(acc[n], (const u32*)&aH, bl[2*n], bl[2*n+1]);
            }
        }
        if (k < 8) gatherO(k+1, (k+1) & 1);
    }

    // epilogue -> g_offm CHW planes
    int rfrag = lane >> 2;
    int cfrag = (lane & 3)*2;
    int coA = mi*16 + rfrag;
    int coB = coA + 8;
#pragma unroll
    for (int n = 0; n < 2; n++){
        int px = px0 + n*8 + cfrag;
        size_t pb = (size_t)h*WW + w0 + px;
#pragma unroll
        for (int half = 0; half < 2; half++){
            int co = half ? coB : coA;
            float d0 = half ? acc[n][2] : acc[n][0];
            float d1 = half ? acc[n][3] : acc[n][1];
            if (co < 18){
                float bb = offb[co];
                *(float2*)(g_offm + ((size_t)(b*27 + co))*HWP + pb) = make_float2(d0+bb, d1+bb);
            } else if (co < 27){
                float bb = modb[co-18];
                float a0 = 2.f/(1.f + __expf(-(d0 + bb)));
                float a1 = 2.f/(1.f + __expf(-(d1 + bb)));
                *(float2*)(g_offm + ((size_t)(b*27 + co))*HWP + pb) = make_float2(a0, a1);
            }
        }
    }
}

// ================= deformable conv via HMMA, pipelined NHWC gather =============
// grid 1024; block 256 (8 warps); tile 64px x 128co. Corner data in regs+shfl.
// MODE 0: out = prelu(conv) -> NHWC d1 (p0 = alpha)
// MODE 1: out = bn2(conv) + x -> CHW d_out (p0 = x CHW)
template<int MODE>
__global__ void __launch_bounds__(256,2)
deform_mma_kernel(const float* __restrict__ src, const uint4* __restrict__ wF,
                  const float* __restrict__ p0,
                  const float* __restrict__ bn_g, const float* __restrict__ bn_b,
                  const float* __restrict__ bn_m, const float* __restrict__ bn_v,
                  float* __restrict__ out){
    extern __shared__ __align__(16) char dsm[];

    int t = threadIdx.x, lane = t & 31, wid = t >> 5;
    int b = blockIdx.x >> 8, rem = blockIdx.x & 255;
    int h = rem >> 1, w0 = (rem & 1) << 6;

    int co0 = (wid >> 1)*32;
    int px0 = (wid & 1)*32;
    int miB = co0 >> 4;

    int sub  = lane & 7;
    int grp  = lane >> 3;
    int lrow = ((grp >> 1) << 3) + sub;
    int lcoff= (grp & 1) << 4;

    u32 smb = smem_to_u32(dsm);

    float acc[2][4][4];
#pragma unroll
    for (int m = 0; m < 2; m++)
#pragma unroll
        for (int n = 0; n < 4; n++)
#pragma unroll
            for (int e = 0; e < 4; e++) acc[m][n][e] = 0.f;

    const float* srcb = src + (size_t)b*HWP*CH;
    const float* offm = g_offm + (size_t)b*27*HWP;

    // per-warp corner regs: lane l<8 owns pixel (wid + l*8)
    int   rad0=0, rad1=0, rad2=0, rad3=0;
    float rwt0=0.f, rwt1=0.f, rwt2=0.f, rwt3=0.f;

    auto corners = [&](int k){
        if (lane < 8){
            int w = w0 + wid + lane*8;
            int p = h*WW + w;
            float oy = offm[(2*k  )*HWP + p];
            float ox = offm[(2*k+1)*HWP + p];
            float mv = offm[(18+k )*HWP + p];
            int ky = k/3, kx = k - ky*3;
            float py  = (float)(h - 1 + ky) + oy;
            float pxf = (float)(w - 1 + kx) + ox;
            float y0f = floorf(py), x0f = floorf(pxf);
            float ay = py - y0f, ax = pxf - x0f;
            int y0 = (int)y0f, x0 = (int)x0f;
#pragma unroll
            for (int j = 0; j < 4; j++){
                int dy = j >> 1, dx = j & 1;
                int yi = y0 + dy, xi = x0 + dx;
                bool ok = ((unsigned)yi < HH) && ((unsigned)xi < WW);
                int yc = min(max(yi, 0), HH-1);
                int xc = min(max(xi, 0), WW-1);
                float wy = dy ? ay : 1.f - ay;
                float wx = dx ? ax : 1.f - ax;
                int   ad = (yc*WW + xc)*CH;
                float wt = ok ? wy*wx*mv : 0.f;
                if (j == 0){ rad0 = ad; rwt0 = wt; }
                else if (j == 1){ rad1 = ad; rwt1 = wt; }
                else if (j == 2){ rad2 = ad; rwt2 = wt; }
                else            { rad3 = ad; rwt3 = wt; }
            }
        }
    };

    auto gather = [&](int buf){
        char* cH = dsm + buf*BUFP;
        char* cL = cH + BUFB;
#pragma unroll
        for (int it = 0; it < 8; it++){
            int a0 = __shfl_sync(0xffffffffu, rad0, it);
            int a1 = __shfl_sync(0xffffffffu, rad1, it);
            int a2 = __shfl_sync(0xffffffffu, rad2, it);
            int a3 = __shfl_sync(0xffffffffu, rad3, it);
            float f0 = __shfl_sync(0xffffffffu, rwt0, it);
            float f1 = __shfl_sync(0xffffffffu, rwt1, it);
            float f2 = __shfl_sync(0xffffffffu, rwt2, it);
            float f3 = __shfl_sync(0xffffffffu, rwt3, it);
            int px = wid + it*8;
            float4 q0 = ((const float4*)(srcb + a0))[lane];
            float4 q1 = ((const float4*)(srcb + a1))[lane];
            float4 q2 = ((const float4*)(srcb + a2))[lane];
            float4 q3 = ((const float4*)(srcb + a3))[lane];
            float4 vv;
            vv.x = f0*q0.x + f1*q1.x + f2*q2.x + f3*q3.x;
            vv.y = f0*q0.y + f1*q1.y + f2*q2.y + f3*q3.y;
            vv.z = f0*q0.z + f1*q1.z + f2*q2.z + f3*q3.z;
            vv.w = f0*q0.w + f1*q1.w + f2*q2.w + f3*q3.w;
            u32 h0,l0,h1,l1;
            cvt_hilo(vv.x, vv.y, h0, l0);
            cvt_hilo(vv.z, vv.w, h1, l1);
            *(uint2*)(cH + px*ROWB + lane*8) = make_uint2(h0, h1);
            *(uint2*)(cL + px*ROWB + lane*8) = make_uint2(l0, l1);
        }
    };

    corners(0);
    gather(0);

    for (int k = 0; k < 9; k++){
        __syncthreads();                 // buf k&1 fully written; prev readers done
        if (k < 8) corners(k+1);         // offm loads issue early
        // HMMA on buf k&1 (3-pass hi/lo, 8 k-steps)
        u32 cHb = smb + (k & 1)*BUFP;
        u32 cLb = cHb + BUFB;
        const uint4* wH = wF + (size_t)(k*2    )*64*32;
        const uint4* wL = wF + (size_t)(k*2 + 1)*64*32;
#pragma unroll
        for (int ki = 0; ki < 8; ki++){
            uint4 aH0 = wH[((miB  )*8 + ki)*32 + lane];
            uint4 aH1 = wH[((miB+1)*8 + ki)*32 + lane];
            uint4 aL0 = wL[((miB  )*8 + ki)*32 + lane];
            uint4 aL1 = wL[((miB+1)*8 + ki)*32 + lane];
            u32 adr0 = (u32)((px0 + lrow)*ROWB + ki*32 + lcoff);
            u32 adr1 = adr0 + 16*ROWB;
            u32 bh[8], bl[8];
            ldmx4(bh    , cHb + adr0);
            ldmx4(bh + 4, cHb + adr1);
            ldmx4(bl    , cLb + adr0);
            ldmx4(bl + 4, cLb + adr1);
#pragma unroll
            for (int n = 0; n < 4; n++){
                u32 b0h = bh[2*n], b1h = bh[2*n+1];
                u32 b0l = bl[2*n], b1l = bl[2*n+1];
                mma_bf16(acc[0][n], (const u32*)&aH0, b0h, b1h);
                mma_bf16(acc[1][n], (const u32*)&aH1, b0h, b1h);
                mma_bf16(acc[0][n], (const u32*)&aL0, b0h, b1h);
                mma_bf16(acc[1][n], (const u32*)&aL1, b0h, b1h);
                mma_bf16(acc[0][n], (const u32*)&aH0, b0l, b1l);
                mma_bf16(acc[1][n], (const u32*)&aH1, b0l, b1l);
            }
        }
        if (k < 8) gather((k+1) & 1);    // fills other buffer, overlaps tensor tail
    }

    // ================= epilogue =================
    int rfrag = lane >> 2;
    int cfrag = (lane & 3)*2;
#pragma unroll
    for (int m = 0; m < 2; m++){
        int coA = co0 + m*16 + rfrag;
        int coB = coA + 8;
        if (MODE == 0){
            float aA = p0[coA], aB = p0[coB];    // alpha
#pragma unroll
            for (int n = 0; n < 4; n++){
                int px = px0 + n*8 + cfrag;
                size_t base = (((size_t)b*HWP) + h*WW + w0 + px)*CH;   // NHWC
                float d0 = acc[m][n][0], d1 = acc[m][n][1];
                float d2 = acc[m][n][2], d3 = acc[m][n][3];
                out[base + coA]      = d0 > 0.f ? d0 : aA*d0;
                out[base + CH + coA] = d1 > 0.f ? d1 : aA*d1;
                out[base + coB]      = d2 > 0.f ? d2 : aB*d2;
                out[base + CH + coB] = d3 > 0.f ? d3 : aB*d3;
            }
        } else {
            float sA  = bn_g[coA] * rsqrtf(bn_v[coA] + 1e-5f);
            float bA  = bn_b[coA] - bn_m[coA]*sA;
            float sB  = bn_g[coB] * rsqrtf(bn_v[coB] + 1e-5f);
            float bB  = bn_b[coB] - bn_m[coB]*sB;
#pragma unroll
            for (int n = 0; n < 4; n++){
                int px = px0 + n*8 + cfrag;
                size_t baseA = ((size_t)(b*CH + coA))*HWP + (size_t)h*WW + w0 + px;
                size_t baseB = baseA + (size_t)8*HWP;
                float2 xA = *(const float2*)(p0 + baseA);
                float2 xB = *(const float2*)(p0 + baseB);
                float d0 = acc[m][n][0], d1 = acc[m][n][1];
                float d2 = acc[m][n][2], d3 = acc[m][n][3];
                *(float2*)(out + baseA) = make_float2(d0*sA + bA + xA.x, d1*sA + bA + xA.y);
                *(float2*)(out + baseB) = make_float2(d2*sB + bB + xB.x, d3*sB + bB + xB.y);
            }
        }
    }
}

// ================= host launcher =================
extern "C" void kernel_launch(void* const* d_in, const int* in_sizes, int n_in,
                              void* d_out, int out_size){
    const float* x      = (const float*)d_in[0];
    const float* bn1_g  = (const float*)d_in[1];
    const float* bn1_b  = (const float*)d_in[2];
    const float* bn1_m  = (const float*)d_in[3];
    const float* bn1_v  = (const float*)d_in[4];
    const float* off1_w = (const float*)d_in[5];
    const float* off1_b = (const float*)d_in[6];
    const float* mod1_w = (const float*)d_in[7];
    const float* mod1_b = (const float*)d_in[8];
    const float* w1     = (const float*)d_in[9];
    const float* alpha  = (const float*)d_in[10];
    const float* off2_w = (const float*)d_in[11];
    const float* off2_b = (const float*)d_in[12];
    const float* mod2_w = (const float*)d_in[13];
    const float* mod2_b = (const float*)d_in[14];
    const float* w2     = (const float*)d_in[15];
    const float* bn2_g  = (const float*)d_in[16];
    const float* bn2_b  = (const float*)d_in[17];
    const float* bn2_m  = (const float*)d_in[18];
    const float* bn2_v  = (const float*)d_in[19];
    float* out = (float*)d_out;

    float *r1p, *d1p;
    uint4 *wf1, *wf2, *of1, *of2;
    cudaGetSymbolAddress((void**)&r1p, g_r1);
    cudaGetSymbolAddress((void**)&d1p, g_d1);
    cudaGetSymbolAddress((void**)&wf1, g_wF1);
    cudaGetSymbolAddress((void**)&wf2, g_wF2);
    cudaGetSymbolAddress((void**)&of1, g_oF1);
    cudaGetSymbolAddress((void**)&of2, g_oF2);

    cudaFuncSetAttribute(offmod_mma_kernel,   cudaFuncAttributeMaxDynamicSharedMemorySize, PIPE_SMEM);
    cudaFuncSetAttribute(deform_mma_kernel<0>, cudaFuncAttributeMaxDynamicSharedMemorySize, PIPE_SMEM);
    cudaFuncSetAttribute(deform_mma_kernel<1>, cudaFuncAttributeMaxDynamicSharedMemorySize, PIPE_SMEM);

    // 1) weight prep
    prep_wf_kernel<<<(73728 + 255)/256, 256>>>(w1, w2);
    prep_of_kernel<<<(18432 + 255)/256, 256>>>(off1_w, mod1_w, off2_w, mod2_w);
    // 2) bn1 -> NHWC r1
    bn1_nhwc_kernel<<<8192, 256>>>(x, bn1_g, bn1_b, bn1_m, bn1_v);
    // 3) offsets + mask for layer 1 (HMMA, pipelined)
    offmod_mma_kernel<<<1024, 256, PIPE_SMEM>>>(r1p, of1, off1_b, mod1_b);
    // 4) deform conv 1 (+prelu) -> NHWC d1
    deform_mma_kernel<0><<<1024, 256, PIPE_SMEM>>>(r1p, wf1, alpha, nullptr, nullptr, nullptr, nullptr, d1p);
    // 5) offsets + mask for layer 2 (HMMA, pipelined)
    offmod_mma_kernel<<<1024, 256, PIPE_SMEM>>>(d1p, of2, off2_b, mod2_b);
    // 6) deform conv 2 (+bn2 +shortcut) -> CHW out
    deform_mma_kernel<1><<<1024, 256, PIPE_SMEM>>>(d1p, wf2, x, bn2_g, bn2_b, bn2_m, bn2_v, out);
}

// round 12
// speedup vs baseline: 5.1666x; 1.0636x over previous
#include <cuda_runtime.h>
#include <cuda_bf16.h>
#include <math.h>
#include <cstdint>

#define BSZ 4
#define CH  128
#define HH  128
#define WW  128
#define HWP (HH*WW)

typedef unsigned long long u64;
typedef uint32_t u32;

// ================= scratch (static device memory) =================
__device__ float g_r1 [(size_t)BSZ*HWP*CH];   // bn1 output, NHWC [b][h][w][c]
__device__ float g_d1 [(size_t)BSZ*HWP*CH];   // layer1 output, NHWC
__device__ float g_offm[(size_t)BSZ*27*HWP];  // CHW planes: 0..17 offsets, 18..26 mask
// deform weights, fragment-packed bf16: [k][prec][mi 8][ki 8][lane 32] uint4
__device__ uint4 g_wF1[9*2*8*8*32];
__device__ uint4 g_wF2[9*2*8*8*32];
// offmod weights (27 rows padded to 32): [k][prec][mi 2][ki 8][lane 32] uint4
__device__ uint4 g_oF1[9*2*2*8*32];
__device__ uint4 g_oF2[9*2*2*8*32];

// ================= helpers =================
__device__ __forceinline__ u32 smem_to_u32(const void* p){
    u32 a; asm("{ .reg .u64 t; cvta.to.shared.u64 t, %1; cvt.u32.u64 %0, t; }" : "=r"(a) : "l"(p));
    return a;
}
__device__ __forceinline__ u32 pack_bf2(float a, float b){
    __nv_bfloat162 h = __floats2bfloat162_rn(a, b);
    return *(u32*)&h;
}
__device__ __forceinline__ void cvt_hilo(float x, float y, u32 &h, u32 &l){
    __nv_bfloat162 h2 = __floats2bfloat162_rn(x, y);
    float2 hf = __bfloat1622float2(h2);
    __nv_bfloat162 l2 = __floats2bfloat162_rn(x - hf.x, y - hf.y);
    h = *(u32*)&h2; l = *(u32*)&l2;
}
__device__ __forceinline__ void mma_bf16(float* d, const u32* a, u32 b0, u32 b1){
    asm volatile(
        "mma.sync.aligned.m16n8k16.row.col.f32.bf16.bf16.f32 "
        "{%0,%1,%2,%3}, {%4,%5,%6,%7}, {%8,%9}, {%0,%1,%2,%3};"
        : "+f"(d[0]), "+f"(d[1]), "+f"(d[2]), "+f"(d[3])
        : "r"(a[0]), "r"(a[1]), "r"(a[2]), "r"(a[3]), "r"(b0), "r"(b1));
}
// non-trans: cols smem is px-major (already B^T) -> direct col-major B fragment
__device__ __forceinline__ void ldmx4(u32* r, u32 addr){
    asm volatile("ldmatrix.sync.aligned.m8n8.x4.shared.b16 {%0,%1,%2,%3}, [%4];"
        : "=r"(r[0]), "=r"(r[1]), "=r"(r[2]), "=r"(r[3]) : "r"(addr));
}

#define ROWB 272
#define BUFB (64*ROWB)        // 17408 bytes per precision tile
#define BUFP (2*BUFB)         // 34816 bytes per (H+L) buffer
#define PIPE_SMEM (2*BUFP)    // 69632 bytes double-buffered (deform)

// offmod patch: [prec 2][row 3][px 66][272B]
#define OPX_STRIDE 272
#define OROW_STRIDE (66*OPX_STRIDE)      // 17952
#define OPREC_STRIDE (3*OROW_STRIDE)     // 53856
#define OFFMOD_SMEM (2*OPREC_STRIDE)     // 107712

// ================= prep: deform weights -> fragment order, bf16 hi/lo ==========
__global__ void prep_wf_kernel(const float* __restrict__ w1, const float* __restrict__ w2){
    int i = blockIdx.x*256 + threadIdx.x;
    if (i >= 73728) return;
    int lane = i & 31;
    int ki   = (i>>5) & 7;
    int mi   = (i>>8) & 7;
    int prec = (i>>11) & 1;
    int rest = i >> 12;            // 0..17
    int k    = rest % 9;
    int layer= rest / 9;
    const float* w = layer ? w2 : w1;

    int r  = lane >> 2;
    int cp = (lane & 3)*2;
    int row0 = mi*16 + r;
    int col0 = ki*16 + cp;

    float v[4][2];
#pragma unroll
    for (int q = 0; q < 4; q++){
        int ro = row0 + ((q & 1) ? 8 : 0);
        int co_ = col0 + ((q >> 1) ? 8 : 0);
#pragma unroll
        for (int e = 0; e < 2; e++){
            float val = w[(ro*CH + (co_+e))*9 + k];
            if (prec){
                float hi = __bfloat162float(__float2bfloat16(val));
                val = val - hi;
            }
            v[q][e] = val;
        }
    }
    uint4 o;
    o.x = pack_bf2(v[0][0], v[0][1]);
    o.y = pack_bf2(v[1][0], v[1][1]);
    o.z = pack_bf2(v[2][0], v[2][1]);
    o.w = pack_bf2(v[3][0], v[3][1]);
    uint4* dst = layer ? g_wF2 : g_wF1;
    dst[(((k*2 + prec)*8 + mi)*8 + ki)*32 + lane] = o;
}

// ================= prep: offmod weights (27 co pad 32) -> fragments ============
__global__ void prep_of_kernel(const float* __restrict__ o1w, const float* __restrict__ m1w,
                               const float* __restrict__ o2w, const float* __restrict__ m2w){
    int i = blockIdx.x*256 + threadIdx.x;
    if (i >= 18432) return;
    int lane = i & 31;
    int ki   = (i>>5) & 7;
    int mi   = (i>>8) & 1;
    int prec = (i>>9) & 1;
    int rest = i >> 10;            // 0..17
    int k    = rest % 9;
    int layer= rest / 9;
    const float* ow = layer ? o2w : o1w;
    const float* mw = layer ? m2w : m1w;

    int r  = lane >> 2;
    int cp = (lane & 3)*2;
    int row0 = mi*16 + r;
    int col0 = ki*16 + cp;

    float v[4][2];
#pragma unroll
    for (int q = 0; q < 4; q++){
        int ro = row0 + ((q & 1) ? 8 : 0);
        int c_ = col0 + ((q >> 1) ? 8 : 0);
#pragma unroll
        for (int e = 0; e < 2; e++){
            int c = c_ + e;
            float val = 0.f;
            if (ro < 18)      val = ow[(ro*CH + c)*9 + k];
            else if (ro < 27) val = mw[((ro-18)*CH + c)*9 + k];
            if (prec){
                float hi = __bfloat162float(__float2bfloat16(val));
                val = val - hi;
            }
            v[q][e] = val;
        }
    }
    uint4 o;
    o.x = pack_bf2(v[0][0], v[0][1]);
    o.y = pack_bf2(v[1][0], v[1][1]);
    o.z = pack_bf2(v[2][0], v[2][1]);
    o.w = pack_bf2(v[3][0], v[3][1]);
    uint4* dst = layer ? g_oF2 : g_oF1;
    dst[(((k*2 + prec)*2 + mi)*8 + ki)*32 + lane] = o;
}

// ================= bn1 + transpose to NHWC =================
__global__ void bn1_nhwc_kernel(const float* __restrict__ x,
                                const float* __restrict__ g, const float* __restrict__ b_,
                                const float* __restrict__ m, const float* __restrict__ v){
    __shared__ float tile[32][33];
    int bid = blockIdx.x;
    int wb = bid & 3, cb = (bid >> 2) & 3, h = (bid >> 4) & 127, b = bid >> 11;
    int tx = threadIdx.x & 31, ty = threadIdx.x >> 5;
    int c0 = cb*32, w0 = wb*32;
#pragma unroll
    for (int i = 0; i < 4; i++){
        int c = c0 + ty + i*8;
        float s  = g[c] * rsqrtf(v[c] + 1e-5f);
        float bb = b_[c] - m[c]*s;
        float xv = x[((size_t)(b*CH + c))*HWP + h*WW + w0 + tx];
        tile[ty + i*8][tx] = xv*s + bb;
    }
    __syncthreads();
#pragma unroll
    for (int i = 0; i < 4; i++){
        int w = w0 + ty + i*8;
        g_r1[(((size_t)b*HWP) + h*WW + w)*CH + c0 + tx] = tile[tx][ty + i*8];
    }
}

// ================= offmod via HMMA, shared 3-row patch (load once, 9 taps) =====
// grid 1024 = b*h*2half; block 256 (8 warps). M=32(27), N=64px, K=128/tap x 9 taps.
// Patch smem: [prec][row 3][px 66][272B]; px index 0 <-> x = w0-1.
__global__ void __launch_bounds__(256,2)
offmod_mma_kernel(const float* __restrict__ src, const uint4* __restrict__ oF,
                  const float* __restrict__ offb, const float* __restrict__ modb){
    extern __shared__ __align__(16) char dsm[];

    int t = threadIdx.x, lane = t & 31, wid = t >> 5;
    int b = blockIdx.x >> 8, rem = blockIdx.x & 255;
    int h = rem >> 1, w0 = (rem & 1) << 6;

    int mi  = wid >> 2;            // 0..1
    int px0 = (wid & 3) * 16;

    int sub  = lane & 7;
    int grp  = lane >> 3;
    int lrow = ((grp >> 1) << 3) + sub;
    int lcoff= (grp & 1) << 4;

    u32 smb = smem_to_u32(dsm);
    const float* srcb = src + (size_t)b*HWP*CH;

    // ---- load 3x66 patch once, cvt to bf16 hi/lo ----
    // slot i: pair = i>>3 (row*66+px), sub8 = i&7 -> channels sub8*16..+15
    for (int i = t; i < 198*8; i += 256){
        int pair = i >> 3;
        int s8   = i & 7;
        int row  = pair / 66;
        int px   = pair - row*66;
        int y = h - 1 + row;
        int x = w0 - 1 + px;
        int c0 = s8*16;
        bool ok = ((unsigned)y < HH) && ((unsigned)x < WW);
        const float4* sp = (const float4*)(srcb + ((size_t)y*WW + x)*CH + c0);
        char* pH = dsm + row*OROW_STRIDE + px*OPX_STRIDE + c0*2;
        char* pL = pH + OPREC_STRIDE;
#pragma unroll
        for (int q = 0; q < 4; q++){
            float4 vv = ok ? sp[q] : make_float4(0.f,0.f,0.f,0.f);
            u32 h0,l0,h1,l1;
            cvt_hilo(vv.x, vv.y, h0, l0);
            cvt_hilo(vv.z, vv.w, h1, l1);
            *(uint2*)(pH + q*8) = make_uint2(h0, h1);
            *(uint2*)(pL + q*8) = make_uint2(l0, l1);
        }
    }
    __syncthreads();

    float acc[2][4];
#pragma unroll
    for (int n = 0; n < 2; n++)
#pragma unroll
        for (int e = 0; e < 4; e++) acc[n][e] = 0.f;

#pragma unroll
    for (int k = 0; k < 9; k++){
        int ky = k/3, kx = k - ky*3;
        u32 cHb = smb + ky*OROW_STRIDE + (px0 + lrow + kx)*OPX_STRIDE + lcoff;
        u32 cLb = cHb + OPREC_STRIDE;
        const uint4* wH = oF + (size_t)(((k*2    )*2 + mi)*8)*32;
        const uint4* wL = oF + (size_t)(((k*2 + 1)*2 + mi)*8)*32;
#pragma unroll
        for (int ki = 0; ki < 8; ki++){
            uint4 aH = wH[ki*32 + lane];
            uint4 aL = wL[ki*32 + lane];
            u32 bh[4], bl[4];
            ldmx4(bh, cHb + ki*32);
            ldmx4(bl, cLb + ki*32);
#pragma unroll
            for (int n = 0; n < 2; n++){
                mma_bf16(acc[n], (const u32*)&aH, bh[2*n], bh[2*n+1]);
                mma_bf16(acc[n], (const u32*)&aL, bh[2*n], bh[2*n+1]);
                mma_bf16(acc[n], (const u32*)&aH, bl[2*n], bl[2*n+1]);
            }
        }
    }

    // epilogue -> g_offm CHW planes
    int rfrag = lane >> 2;
    int cfrag = (lane & 3)*2;
    int coA = mi*16 + rfrag;
    int coB = coA + 8;
#pragma unroll
    for (int n = 0; n < 2; n++){
        int px = px0 + n*8 + cfrag;
        size_t pb = (size_t)h*WW + w0 + px;
#pragma unroll
        for (int half = 0; half < 2; half++){
            int co = half ? coB : coA;
            float d0 = half ? acc[n][2] : acc[n][0];
            float d1 = half ? acc[n][3] : acc[n][1];
            if (co < 18){
                float bb = offb[co];
                *(float2*)(g_offm + ((size_t)(b*27 + co))*HWP + pb) = make_float2(d0+bb, d1+bb);
            } else if (co < 27){
                float bb = modb[co-18];
                float a0 = 2.f/(1.f + __expf(-(d0 + bb)));
                float a1 = 2.f/(1.f + __expf(-(d1 + bb)));
                *(float2*)(g_offm + ((size_t)(b*27 + co))*HWP + pb) = make_float2(a0, a1);
            }
        }
    }
}

// ================= deformable conv via HMMA, pipelined NHWC gather =============
// (unchanged from R11 passing version)
template<int MODE>
__global__ void __launch_bounds__(256,2)
deform_mma_kernel(const float* __restrict__ src, const uint4* __restrict__ wF,
                  const float* __restrict__ p0,
                  const float* __restrict__ bn_g, const float* __restrict__ bn_b,
                  const float* __restrict__ bn_m, const float* __restrict__ bn_v,
                  float* __restrict__ out){
    extern __shared__ __align__(16) char dsm[];

    int t = threadIdx.x, lane = t & 31, wid = t >> 5;
    int b = blockIdx.x >> 8, rem = blockIdx.x & 255;
    int h = rem >> 1, w0 = (rem & 1) << 6;

    int co0 = (wid >> 1)*32;
    int px0 = (wid & 1)*32;
    int miB = co0 >> 4;

    int sub  = lane & 7;
    int grp  = lane >> 3;
    int lrow = ((grp >> 1) << 3) + sub;
    int lcoff= (grp & 1) << 4;

    u32 smb = smem_to_u32(dsm);

    float acc[2][4][4];
#pragma unroll
    for (int m = 0; m < 2; m++)
#pragma unroll
        for (int n = 0; n < 4; n++)
#pragma unroll
            for (int e = 0; e < 4; e++) acc[m][n][e] = 0.f;

    const float* srcb = src + (size_t)b*HWP*CH;
    const float* offm = g_offm + (size_t)b*27*HWP;

    int   rad0=0, rad1=0, rad2=0, rad3=0;
    float rwt0=0.f, rwt1=0.f, rwt2=0.f, rwt3=0.f;

    auto corners = [&](int k){
        if (lane < 8){
            int w = w0 + wid + lane*8;
            int p = h*WW + w;
            float oy = offm[(2*k  )*HWP + p];
            float ox = offm[(2*k+1)*HWP + p];
            float mv = offm[(18+k )*HWP + p];
            int ky = k/3, kx = k - ky*3;
            float py  = (float)(h - 1 + ky) + oy;
            float pxf = (float)(w - 1 + kx) + ox;
            float y0f = floorf(py), x0f = floorf(pxf);
            float ay = py - y0f, ax = pxf - x0f;
            int y0 = (int)y0f, x0 = (int)x0f;
#pragma unroll
            for (int j = 0; j < 4; j++){
                int dy = j >> 1, dx = j & 1;
                int yi = y0 + dy, xi = x0 + dx;
                bool ok = ((unsigned)yi < HH) && ((unsigned)xi < WW);
                int yc = min(max(yi, 0), HH-1);
                int xc = min(max(xi, 0), WW-1);
                float wy = dy ? ay : 1.f - ay;
                float wx = dx ? ax : 1.f - ax;
                int   ad = (yc*WW + xc)*CH;
                float wt = ok ? wy*wx*mv : 0.f;
                if (j == 0){ rad0 = ad; rwt0 = wt; }
                else if (j == 1){ rad1 = ad; rwt1 = wt; }
                else if (j == 2){ rad2 = ad; rwt2 = wt; }
                else            { rad3 = ad; rwt3 = wt; }
            }
        }
    };

    auto gather = [&](int buf){
        char* cH = dsm + buf*BUFP;
        char* cL = cH + BUFB;
#pragma unroll
        for (int it = 0; it < 8; it++){
            int a0 = __shfl_sync(0xffffffffu, rad0, it);
            int a1 = __shfl_sync(0xffffffffu, rad1, it);
            int a2 = __shfl_sync(0xffffffffu, rad2, it);
            int a3 = __shfl_sync(0xffffffffu, rad3, it);
            float f0 = __shfl_sync(0xffffffffu, rwt0, it);
            float f1 = __shfl_sync(0xffffffffu, rwt1, it);
            float f2 = __shfl_sync(0xffffffffu, rwt2, it);
            float f3 = __shfl_sync(0xffffffffu, rwt3, it);
            int px = wid + it*8;
            float4 q0 = ((const float4*)(srcb + a0))[lane];
            float4 q1 = ((const float4*)(srcb + a1))[lane];
            float4 q2 = ((const float4*)(srcb + a2))[lane];
            float4 q3 = ((const float4*)(srcb + a3))[lane];
            float4 vv;
            vv.x = f0*q0.x + f1*q1.x + f2*q2.x + f3*q3.x;
            vv.y = f0*q0.y + f1*q1.y + f2*q2.y + f3*q3.y;
            vv.z = f0*q0.z + f1*q1.z + f2*q2.z + f3*q3.z;
            vv.w = f0*q0.w + f1*q1.w + f2*q2.w + f3*q3.w;
            u32 h0,l0,h1,l1;
            cvt_hilo(vv.x, vv.y, h0, l0);
            cvt_hilo(vv.z, vv.w, h1, l1);
            *(uint2*)(cH + px*ROWB + lane*8) = make_uint2(h0, h1);
            *(uint2*)(cL + px*ROWB + lane*8) = make_uint2(l0, l1);
        }
    };

    corners(0);
    gather(0);

    for (int k = 0; k < 9; k++){
        __syncthreads();
        if (k < 8) corners(k+1);
        u32 cHb = smb + (k & 1)*BUFP;
        u32 cLb = cHb + BUFB;
        const uint4* wH = wF + (size_t)(k*2    )*64*32;
        const uint4* wL = wF + (size_t)(k*2 + 1)*64*32;
#pragma unroll
        for (int ki = 0; ki < 8; ki++){
            uint4 aH0 = wH[((miB  )*8 + ki)*32 + lane];
            uint4 aH1 = wH[((miB+1)*8 + ki)*32 + lane];
            uint4 aL0 = wL[((miB  )*8 + ki)*32 + lane];
            uint4 aL1 = wL[((miB+1)*8 + ki)*32 + lane];
            u32 adr0 = (u32)((px0 + lrow)*ROWB + ki*32 + lcoff);
            u32 adr1 = adr0 + 16*ROWB;
            u32 bh[8], bl[8];
            ldmx4(bh    , cHb + adr0);
            ldmx4(bh + 4, cHb + adr1);
            ldmx4(bl    , cLb + adr0);
            ldmx4(bl + 4, cLb + adr1);
#pragma unroll
            for (int n = 0; n < 4; n++){
                u32 b0h = bh[2*n], b1h = bh[2*n+1];
                u32 b0l = bl[2*n], b1l = bl[2*n+1];
                mma_bf16(acc[0][n], (const u32*)&aH0, b0h, b1h);
                mma_bf16(acc[1][n], (const u32*)&aH1, b0h, b1h);
                mma_bf16(acc[0][n], (const u32*)&aL0, b0h, b1h);
                mma_bf16(acc[1][n], (const u32*)&aL1, b0h, b1h);
                mma_bf16(acc[0][n], (const u32*)&aH0, b0l, b1l);
                mma_bf16(acc[1][n], (const u32*)&aH1, b0l, b1l);
            }
        }
        if (k < 8) gather((k+1) & 1);
    }

    // ================= epilogue =================
    int rfrag = lane >> 2;
    int cfrag = (lane & 3)*2;
#pragma unroll
    for (int m = 0; m < 2; m++){
        int coA = co0 + m*16 + rfrag;
        int coB = coA + 8;
        if (MODE == 0){
            float aA = p0[coA], aB = p0[coB];
#pragma unroll
            for (int n = 0; n < 4; n++){
                int px = px0 + n*8 + cfrag;
                size_t base = (((size_t)b*HWP) + h*WW + w0 + px)*CH;   // NHWC
                float d0 = acc[m][n][0], d1 = acc[m][n][1];
                float d2 = acc[m][n][2], d3 = acc[m][n][3];
                out[base + coA]      = d0 > 0.f ? d0 : aA*d0;
                out[base + CH + coA] = d1 > 0.f ? d1 : aA*d1;
                out[base + coB]      = d2 > 0.f ? d2 : aB*d2;
                out[base + CH + coB] = d3 > 0.f ? d3 : aB*d3;
            }
        } else {
            float sA  = bn_g[coA] * rsqrtf(bn_v[coA] + 1e-5f);
            float bA  = bn_b[coA] - bn_m[coA]*sA;
            float sB  = bn_g[coB] * rsqrtf(bn_v[coB] + 1e-5f);
            float bB  = bn_b[coB] - bn_m[coB]*sB;
#pragma unroll
            for (int n = 0; n < 4; n++){
                int px = px0 + n*8 + cfrag;
                size_t baseA = ((size_t)(b*CH + coA))*HWP + (size_t)h*WW + w0 + px;
                size_t baseB = baseA + (size_t)8*HWP;
                float2 xA = *(const float2*)(p0 + baseA);
                float2 xB = *(const float2*)(p0 + baseB);
                float d0 = acc[m][n][0], d1 = acc[m][n][1];
                float d2 = acc[m][n][2], d3 = acc[m][n][3];
                *(float2*)(out + baseA) = make_float2(d0*sA + bA + xA.x, d1*sA + bA + xA.y);
                *(float2*)(out + baseB) = make_float2(d2*sB + bB + xB.x, d3*sB + bB + xB.y);
            }
        }
    }
}

// ================= host launcher =================
extern "C" void kernel_launch(void* const* d_in, const int* in_sizes, int n_in,
                              void* d_out, int out_size){
    const float* x      = (const float*)d_in[0];
    const float* bn1_g  = (const float*)d_in[1];
    const float* bn1_b  = (const float*)d_in[2];
    const float* bn1_m  = (const float*)d_in[3];
    const float* bn1_v  = (const float*)d_in[4];
    const float* off1_w = (const float*)d_in[5];
    const float* off1_b = (const float*)d_in[6];
    const float* mod1_w = (const float*)d_in[7];
    const float* mod1_b = (const float*)d_in[8];
    const float* w1     = (const float*)d_in[9];
    const float* alpha  = (const float*)d_in[10];
    const float* off2_w = (const float*)d_in[11];
    const float* off2_b = (const float*)d_in[12];
    const float* mod2_w = (const float*)d_in[13];
    const float* mod2_b = (const float*)d_in[14];
    const float* w2     = (const float*)d_in[15];
    const float* bn2_g  = (const float*)d_in[16];
    const float* bn2_b  = (const float*)d_in[17];
    const float* bn2_m  = (const float*)d_in[18];
    const float* bn2_v  = (const float*)d_in[19];
    float* out = (float*)d_out;

    float *r1p, *d1p;
    uint4 *wf1, *wf2, *of1, *of2;
    cudaGetSymbolAddress((void**)&r1p, g_r1);
    cudaGetSymbolAddress((void**)&d1p, g_d1);
    cudaGetSymbolAddress((void**)&wf1, g_wF1);
    cudaGetSymbolAddress((void**)&wf2, g_wF2);
    cudaGetSymbolAddress((void**)&of1, g_oF1);
    cudaGetSymbolAddress((void**)&of2, g_oF2);

    cudaFuncSetAttribute(offmod_mma_kernel,    cudaFuncAttributeMaxDynamicSharedMemorySize, OFFMOD_SMEM);
    cudaFuncSetAttribute(deform_mma_kernel<0>, cudaFuncAttributeMaxDynamicSharedMemorySize, PIPE_SMEM);
    cudaFuncSetAttribute(deform_mma_kernel<1>, cudaFuncAttributeMaxDynamicSharedMemorySize, PIPE_SMEM);

    // 1) weight prep
    prep_wf_kernel<<<(73728 + 255)/256, 256>>>(w1, w2);
    prep_of_kernel<<<(18432 + 255)/256, 256>>>(off1_w, mod1_w, off2_w, mod2_w);
    // 2) bn1 -> NHWC r1
    bn1_nhwc_kernel<<<8192, 256>>>(x, bn1_g, bn1_b, bn1_m, bn1_v);
    // 3) offsets + mask for layer 1 (HMMA, shared patch)
    offmod_mma_kernel<<<1024, 256, OFFMOD_SMEM>>>(r1p, of1, off1_b, mod1_b);
    // 4) deform conv 1 (+prelu) -> NHWC d1
    deform_mma_kernel<0><<<1024, 256, PIPE_SMEM>>>(r1p, wf1, alpha, nullptr, nullptr, nullptr, nullptr, d1p);
    // 5) offsets + mask for layer 2 (HMMA, shared patch)
    offmod_mma_kernel<<<1024, 256, OFFMOD_SMEM>>>(d1p, of2, off2_b, mod2_b);
    // 6) deform conv 2 (+bn2 +shortcut) -> CHW out
    deform_mma_kernel<1><<<1024, 256, PIPE_SMEM>>>(d1p, wf2, x, bn2_g, bn2_b, bn2_m, bn2_v, out);
}

// round 13
// speedup vs baseline: 7.4938x; 1.4504x over previous
#include <cuda_runtime.h>
#include <cuda_fp16.h>
#include <math.h>
#include <cstdint>

#define BSZ 4
#define CH  128
#define HH  128
#define WW  128
#define HWP (HH*WW)

typedef unsigned long long u64;
typedef uint32_t u32;

// ================= scratch (static device memory) =================
__device__ float g_r1 [(size_t)BSZ*HWP*CH];   // bn1 output, NHWC [b][h][w][c]
__device__ float g_d1 [(size_t)BSZ*HWP*CH];   // layer1 output, NHWC
__device__ float g_offm[(size_t)BSZ*27*HWP];  // CHW planes: 0..17 offsets, 18..26 mask
// deform weights, fragment-packed fp16: [k][mi 8][ki 8][lane 32] uint4
__device__ uint4 g_wF1[9*8*8*32];
__device__ uint4 g_wF2[9*8*8*32];
// offmod weights (27 rows padded to 32): [k][mi 2][ki 8][lane 32] uint4
__device__ uint4 g_oF1[9*2*8*32];
__device__ uint4 g_oF2[9*2*8*32];

// ================= helpers =================
__device__ __forceinline__ u32 smem_to_u32(const void* p){
    u32 a; asm("{ .reg .u64 t; cvta.to.shared.u64 t, %1; cvt.u32.u64 %0, t; }" : "=r"(a) : "l"(p));
    return a;
}
__device__ __forceinline__ u32 pack_h2(float a, float b){
    __half2 h = __floats2half2_rn(a, b);
    return *(u32*)&h;
}
__device__ __forceinline__ void mma_f16(float* d, const u32* a, u32 b0, u32 b1){
    asm volatile(
        "mma.sync.aligned.m16n8k16.row.col.f32.f16.f16.f32 "
        "{%0,%1,%2,%3}, {%4,%5,%6,%7}, {%8,%9}, {%0,%1,%2,%3};"
        : "+f"(d[0]), "+f"(d[1]), "+f"(d[2]), "+f"(d[3])
        : "r"(a[0]), "r"(a[1]), "r"(a[2]), "r"(a[3]), "r"(b0), "r"(b1));
}
// non-trans: cols smem is px-major (already B^T) -> direct col-major B fragment
__device__ __forceinline__ void ldmx4(u32* r, u32 addr){
    asm volatile("ldmatrix.sync.aligned.m8n8.x4.shared.b16 {%0,%1,%2,%3}, [%4];"
        : "=r"(r[0]), "=r"(r[1]), "=r"(r[2]), "=r"(r[3]) : "r"(addr));
}

#define ROWB 272
#define BUFB (64*ROWB)        // 17408 bytes per cols buffer (fp16 single)
#define PIPE_SMEM (2*BUFB)    // 34816 bytes double-buffered (deform)

// offmod patch: [row 3][px 66][272B] fp16
#define OPX_STRIDE 272
#define OROW_STRIDE (66*OPX_STRIDE)      // 17952
#define OFFMOD_SMEM (3*OROW_STRIDE)      // 53856

// ================= prep: deform weights -> fragment order, fp16 ================
__global__ void prep_wf_kernel(const float* __restrict__ w1, const float* __restrict__ w2){
    int i = blockIdx.x*256 + threadIdx.x;
    if (i >= 36864) return;
    int lane = i & 31;
    int ki   = (i>>5) & 7;
    int mi   = (i>>8) & 7;
    int rest = i >> 11;            // 0..17
    int k    = rest % 9;
    int layer= rest / 9;
    const float* w = layer ? w2 : w1;

    int r  = lane >> 2;
    int cp = (lane & 3)*2;
    int row0 = mi*16 + r;
    int col0 = ki*16 + cp;

    float v[4][2];
#pragma unroll
    for (int q = 0; q < 4; q++){
        int ro = row0 + ((q & 1) ? 8 : 0);
        int co_ = col0 + ((q >> 1) ? 8 : 0);
#pragma unroll
        for (int e = 0; e < 2; e++)
            v[q][e] = w[(ro*CH + (co_+e))*9 + k];
    }
    uint4 o;
    o.x = pack_h2(v[0][0], v[0][1]);
    o.y = pack_h2(v[1][0], v[1][1]);
    o.z = pack_h2(v[2][0], v[2][1]);
    o.w = pack_h2(v[3][0], v[3][1]);
    uint4* dst = layer ? g_wF2 : g_wF1;
    dst[((k*8 + mi)*8 + ki)*32 + lane] = o;
}

// ================= prep: offmod weights (27 co pad 32) -> fragments ============
__global__ void prep_of_kernel(const float* __restrict__ o1w, const float* __restrict__ m1w,
                               const float* __restrict__ o2w, const float* __restrict__ m2w){
    int i = blockIdx.x*256 + threadIdx.x;
    if (i >= 9216) return;
    int lane = i & 31;
    int ki   = (i>>5) & 7;
    int mi   = (i>>8) & 1;
    int rest = i >> 9;             // 0..17
    int k    = rest % 9;
    int layer= rest / 9;
    const float* ow = layer ? o2w : o1w;
    const float* mw = layer ? m2w : m1w;

    int r  = lane >> 2;
    int cp = (lane & 3)*2;
    int row0 = mi*16 + r;
    int col0 = ki*16 + cp;

    float v[4][2];
#pragma unroll
    for (int q = 0; q < 4; q++){
        int ro = row0 + ((q & 1) ? 8 : 0);
        int c_ = col0 + ((q >> 1) ? 8 : 0);
#pragma unroll
        for (int e = 0; e < 2; e++){
            int c = c_ + e;
            float val = 0.f;
            if (ro < 18)      val = ow[(ro*CH + c)*9 + k];
            else if (ro < 27) val = mw[((ro-18)*CH + c)*9 + k];
            v[q][e] = val;
        }
    }
    uint4 o;
    o.x = pack_h2(v[0][0], v[0][1]);
    o.y = pack_h2(v[1][0], v[1][1]);
    o.z = pack_h2(v[2][0], v[2][1]);
    o.w = pack_h2(v[3][0], v[3][1]);
    uint4* dst = layer ? g_oF2 : g_oF1;
    dst[((k*2 + mi)*8 + ki)*32 + lane] = o;
}

// ================= bn1 + transpose to NHWC =================
__global__ void bn1_nhwc_kernel(const float* __restrict__ x,
                                const float* __restrict__ g, const float* __restrict__ b_,
                                const float* __restrict__ m, const float* __restrict__ v){
    __shared__ float tile[32][33];
    int bid = blockIdx.x;
    int wb = bid & 3, cb = (bid >> 2) & 3, h = (bid >> 4) & 127, b = bid >> 11;
    int tx = threadIdx.x & 31, ty = threadIdx.x >> 5;
    int c0 = cb*32, w0 = wb*32;
#pragma unroll
    for (int i = 0; i < 4; i++){
        int c = c0 + ty + i*8;
        float s  = g[c] * rsqrtf(v[c] + 1e-5f);
        float bb = b_[c] - m[c]*s;
        float xv = x[((size_t)(b*CH + c))*HWP + h*WW + w0 + tx];
        tile[ty + i*8][tx] = xv*s + bb;
    }
    __syncthreads();
#pragma unroll
    for (int i = 0; i < 4; i++){
        int w = w0 + ty + i*8;
        g_r1[(((size_t)b*HWP) + h*WW + w)*CH + c0 + tx] = tile[tx][ty + i*8];
    }
}

// ================= offmod via HMMA fp16, shared 3-row patch =====================
// grid 1024 = b*h*2half; block 256 (8 warps). M=32(27), N=64px, K=128/tap x 9 taps.
__global__ void __launch_bounds__(256,3)
offmod_mma_kernel(const float* __restrict__ src, const uint4* __restrict__ oF,
                  const float* __restrict__ offb, const float* __restrict__ modb){
    extern __shared__ __align__(16) char dsm[];

    int t = threadIdx.x, lane = t & 31, wid = t >> 5;
    int b = blockIdx.x >> 8, rem = blockIdx.x & 255;
    int h = rem >> 1, w0 = (rem & 1) << 6;

    int mi  = wid >> 2;            // 0..1
    int px0 = (wid & 3) * 16;

    int sub  = lane & 7;
    int grp  = lane >> 3;
    int lrow = ((grp >> 1) << 3) + sub;
    int lcoff= (grp & 1) << 4;

    u32 smb = smem_to_u32(dsm);
    const float* srcb = src + (size_t)b*HWP*CH;

    // ---- load 3x66 patch once, cvt to fp16 ----
    for (int i = t; i < 198*8; i += 256){
        int pair = i >> 3;
        int s8   = i & 7;
        int row  = pair / 66;
        int px   = pair - row*66;
        int y = h - 1 + row;
        int x = w0 - 1 + px;
        int c0 = s8*16;
        bool ok = ((unsigned)y < HH) && ((unsigned)x < WW);
        const float4* sp = (const float4*)(srcb + ((size_t)y*WW + x)*CH + c0);
        char* pH = dsm + row*OROW_STRIDE + px*OPX_STRIDE + c0*2;
#pragma unroll
        for (int q = 0; q < 4; q++){
            float4 vv = ok ? sp[q] : make_float4(0.f,0.f,0.f,0.f);
            *(uint2*)(pH + q*8) = make_uint2(pack_h2(vv.x, vv.y), pack_h2(vv.z, vv.w));
        }
    }
    __syncthreads();

    float acc[2][4];
#pragma unroll
    for (int n = 0; n < 2; n++)
#pragma unroll
        for (int e = 0; e < 4; e++) acc[n][e] = 0.f;

#pragma unroll
    for (int k = 0; k < 9; k++){
        int ky = k/3, kx = k - ky*3;
        u32 cHb = smb + ky*OROW_STRIDE + (px0 + lrow + kx)*OPX_STRIDE + lcoff;
        const uint4* wH = oF + (size_t)((k*2 + mi)*8)*32;
#pragma unroll
        for (int ki = 0; ki < 8; ki++){
            uint4 aH = wH[ki*32 + lane];
            u32 bh[4];
            ldmx4(bh, cHb + ki*32);
#pragma unroll
            for (int n = 0; n < 2; n++)
                mma_f16(acc[n], (const u32*)&aH, bh[2*n], bh[2*n+1]);
        }
    }

    // epilogue -> g_offm CHW planes
    int rfrag = lane >> 2;
    int cfrag = (lane & 3)*2;
    int coA = mi*16 + rfrag;
    int coB = coA + 8;
#pragma unroll
    for (int n = 0; n < 2; n++){
        int px = px0 + n*8 + cfrag;
        size_t pb = (size_t)h*WW + w0 + px;
#pragma unroll
        for (int half = 0; half < 2; half++){
            int co = half ? coB : coA;
            float d0 = half ? acc[n][2] : acc[n][0];
            float d1 = half ? acc[n][3] : acc[n][1];
            if (co < 18){
                float bb = offb[co];
                *(float2*)(g_offm + ((size_t)(b*27 + co))*HWP + pb) = make_float2(d0+bb, d1+bb);
            } else if (co < 27){
                float bb = modb[co-18];
                float a0 = 2.f/(1.f + __expf(-(d0 + bb)));
                float a1 = 2.f/(1.f + __expf(-(d1 + bb)));
                *(float2*)(g_offm + ((size_t)(b*27 + co))*HWP + pb) = make_float2(a0, a1);
            }
        }
    }
}

// ================= deformable conv via fp16 HMMA, pipelined NHWC gather =========
// grid 1024; block 256 (8 warps); tile 64px x 128co. Corner data in regs+shfl.
// MODE 0: out = prelu(conv) -> NHWC d1 (p0 = alpha)
// MODE 1: out = bn2(conv) + x -> CHW d_out (p0 = x CHW)
template<int MODE>
__global__ void __launch_bounds__(256,2)
deform_mma_kernel(const float* __restrict__ src, const uint4* __restrict__ wF,
                  const float* __restrict__ p0,
                  const float* __restrict__ bn_g, const float* __restrict__ bn_b,
                  const float* __restrict__ bn_m, const float* __restrict__ bn_v,
                  float* __restrict__ out){
    extern __shared__ __align__(16) char dsm[];

    int t = threadIdx.x, lane = t & 31, wid = t >> 5;
    int b = blockIdx.x >> 8, rem = blockIdx.x & 255;
    int h = rem >> 1, w0 = (rem & 1) << 6;

    int co0 = (wid >> 1)*32;
    int px0 = (wid & 1)*32;
    int miB = co0 >> 4;

    int sub  = lane & 7;
    int grp  = lane >> 3;
    int lrow = ((grp >> 1) << 3) + sub;
    int lcoff= (grp & 1) << 4;

    u32 smb = smem_to_u32(dsm);

    float acc[2][4][4];
#pragma unroll
    for (int m = 0; m < 2; m++)
#pragma unroll
        for (int n = 0; n < 4; n++)
#pragma unroll
            for (int e = 0; e < 4; e++) acc[m][n][e] = 0.f;

    const float* srcb = src + (size_t)b*HWP*CH;
    const float* offm = g_offm + (size_t)b*27*HWP;

    int   rad0=0, rad1=0, rad2=0, rad3=0;
    float rwt0=0.f, rwt1=0.f, rwt2=0.f, rwt3=0.f;

    auto corners = [&](int k){
        if (lane < 8){
            int w = w0 + wid + lane*8;
            int p = h*WW + w;
            float oy = offm[(2*k  )*HWP + p];
            float ox = offm[(2*k+1)*HWP + p];
            float mv = offm[(18+k )*HWP + p];
            int ky = k/3, kx = k - ky*3;
            float py  = (float)(h - 1 + ky) + oy;
            float pxf = (float)(w - 1 + kx) + ox;
            float y0f = floorf(py), x0f = floorf(pxf);
            float ay = py - y0f, ax = pxf - x0f;
            int y0 = (int)y0f, x0 = (int)x0f;
#pragma unroll
            for (int j = 0; j < 4; j++){
                int dy = j >> 1, dx = j & 1;
                int yi = y0 + dy, xi = x0 + dx;
                bool ok = ((unsigned)yi < HH) && ((unsigned)xi < WW);
                int yc = min(max(yi, 0), HH-1);
                int xc = min(max(xi, 0), WW-1);
                float wy = dy ? ay : 1.f - ay;
                float wx = dx ? ax : 1.f - ax;
                int   ad = (yc*WW + xc)*CH;
                float wt = ok ? wy*wx*mv : 0.f;
                if (j == 0){ rad0 = ad; rwt0 = wt; }
                else if (j == 1){ rad1 = ad; rwt1 = wt; }
                else if (j == 2){ rad2 = ad; rwt2 = wt; }
                else            { rad3 = ad; rwt3 = wt; }
            }
        }
    };

    auto gather = [&](int buf){
        char* cH = dsm + buf*BUFB;
#pragma unroll
        for (int it = 0; it < 8; it++){
            int a0 = __shfl_sync(0xffffffffu, rad0, it);
            int a1 = __shfl_sync(0xffffffffu, rad1, it);
            int a2 = __shfl_sync(0xffffffffu, rad2, it);
            int a3 = __shfl_sync(0xffffffffu, rad3, it);
            float f0 = __shfl_sync(0xffffffffu, rwt0, it);
            float f1 = __shfl_sync(0xffffffffu, rwt1, it);
            float f2 = __shfl_sync(0xffffffffu, rwt2, it);
            float f3 = __shfl_sync(0xffffffffu, rwt3, it);
            int px = wid + it*8;
            float4 q0 = ((const float4*)(srcb + a0))[lane];
            float4 q1 = ((const float4*)(srcb + a1))[lane];
            float4 q2 = ((const float4*)(srcb + a2))[lane];
            float4 q3 = ((const float4*)(srcb + a3))[lane];
            float4 vv;
            vv.x = f0*q0.x + f1*q1.x + f2*q2.x + f3*q3.x;
            vv.y = f0*q0.y + f1*q1.y + f2*q2.y + f3*q3.y;
            vv.z = f0*q0.z + f1*q1.z + f2*q2.z + f3*q3.z;
            vv.w = f0*q0.w + f1*q1.w + f2*q2.w + f3*q3.w;
            *(uint2*)(cH + px*ROWB + lane*8) =
                make_uint2(pack_h2(vv.x, vv.y), pack_h2(vv.z, vv.w));
        }
    };

    corners(0);
    gather(0);

    for (int k = 0; k < 9; k++){
        __syncthreads();                 // buf k&1 fully written; prev readers done
        if (k < 8) corners(k+1);
        u32 cHb = smb + (k & 1)*BUFB;
        const uint4* wH = wF + (size_t)(k*8)*8*32;
#pragma unroll
        for (int ki = 0; ki < 8; ki++){
            uint4 aH0 = wH[((miB  )*8 + ki)*32 + lane];
            uint4 aH1 = wH[((miB+1)*8 + ki)*32 + lane];
            u32 adr0 = (u32)((px0 + lrow)*ROWB + ki*32 + lcoff);
            u32 adr1 = adr0 + 16*ROWB;
            u32 bh[8];
            ldmx4(bh    , cHb + adr0);   // n-tiles 0,1
            ldmx4(bh + 4, cHb + adr1);   // n-tiles 2,3
#pragma unroll
            for (int n = 0; n < 4; n++){
                mma_f16(acc[0][n], (const u32*)&aH0, bh[2*n], bh[2*n+1]);
                mma_f16(acc[1][n], (const u32*)&aH1, bh[2*n], bh[2*n+1]);
            }
        }
        if (k < 8) gather((k+1) & 1);
    }

    // ================= epilogue =================
    int rfrag = lane >> 2;
    int cfrag = (lane & 3)*2;
#pragma unroll
    for (int m = 0; m < 2; m++){
        int coA = co0 + m*16 + rfrag;
        int coB = coA + 8;
        if (MODE == 0){
            float aA = p0[coA], aB = p0[coB];
#pragma unroll
            for (int n = 0; n < 4; n++){
                int px = px0 + n*8 + cfrag;
                size_t base = (((size_t)b*HWP) + h*WW + w0 + px)*CH;   // NHWC
                float d0 = acc[m][n][0], d1 = acc[m][n][1];
                float d2 = acc[m][n][2], d3 = acc[m][n][3];
                out[base + coA]      = d0 > 0.f ? d0 : aA*d0;
                out[base + CH + coA] = d1 > 0.f ? d1 : aA*d1;
                out[base + coB]      = d2 > 0.f ? d2 : aB*d2;
                out[base + CH + coB] = d3 > 0.f ? d3 : aB*d3;
            }
        } else {
            float sA  = bn_g[coA] * rsqrtf(bn_v[coA] + 1e-5f);
            float bA  = bn_b[coA] - bn_m[coA]*sA;
            float sB  = bn_g[coB] * rsqrtf(bn_v[coB] + 1e-5f);
            float bB  = bn_b[coB] - bn_m[coB]*sB;
#pragma unroll
            for (int n = 0; n < 4; n++){
                int px = px0 + n*8 + cfrag;
                size_t baseA = ((size_t)(b*CH + coA))*HWP + (size_t)h*WW + w0 + px;
                size_t baseB = baseA + (size_t)8*HWP;
                float2 xA = *(const float2*)(p0 + baseA);
                float2 xB = *(const float2*)(p0 + baseB);
                float d0 = acc[m][n][0], d1 = acc[m][n][1];
                float d2 = acc[m][n][2], d3 = acc[m][n][3];
                *(float2*)(out + baseA) = make_float2(d0*sA + bA + xA.x, d1*sA + bA + xA.y);
                *(float2*)(out + baseB) = make_float2(d2*sB + bB + xB.x, d3*sB + bB + xB.y);
            }
        }
    }
}

// ================= host launcher =================
extern "C" void kernel_launch(void* const* d_in, const int* in_sizes, int n_in,
                              void* d_out, int out_size){
    const float* x      = (const float*)d_in[0];
    const float* bn1_g  = (const float*)d_in[1];
    const float* bn1_b  = (const float*)d_in[2];
    const float* bn1_m  = (const float*)d_in[3];
    const float* bn1_v  = (const float*)d_in[4];
    const float* off1_w = (const float*)d_in[5];
    const float* off1_b = (const float*)d_in[6];
    const float* mod1_w = (const float*)d_in[7];
    const float* mod1_b = (const float*)d_in[8];
    const float* w1     = (const float*)d_in[9];
    const float* alpha  = (const float*)d_in[10];
    const float* off2_w = (const float*)d_in[11];
    const float* off2_b = (const float*)d_in[12];
    const float* mod2_w = (const float*)d_in[13];
    const float* mod2_b = (const float*)d_in[14];
    const float* w2     = (const float*)d_in[15];
    const float* bn2_g  = (const float*)d_in[16];
    const float* bn2_b  = (const float*)d_in[17];
    const float* bn2_m  = (const float*)d_in[18];
    const float* bn2_v  = (const float*)d_in[19];
    float* out = (float*)d_out;

    float *r1p, *d1p;
    uint4 *wf1, *wf2, *of1, *of2;
    cudaGetSymbolAddress((void**)&r1p, g_r1);
    cudaGetSymbolAddress((void**)&d1p, g_d1);
    cudaGetSymbolAddress((void**)&wf1, g_wF1);
    cudaGetSymbolAddress((void**)&wf2, g_wF2);
    cudaGetSymbolAddress((void**)&of1, g_oF1);
    cudaGetSymbolAddress((void**)&of2, g_oF2);

    cudaFuncSetAttribute(offmod_mma_kernel,    cudaFuncAttributeMaxDynamicSharedMemorySize, OFFMOD_SMEM);
    cudaFuncSetAttribute(deform_mma_kernel<0>, cudaFuncAttributeMaxDynamicSharedMemorySize, PIPE_SMEM);
    cudaFuncSetAttribute(deform_mma_kernel<1>, cudaFuncAttributeMaxDynamicSharedMemorySize, PIPE_SMEM);

    // 1) weight prep (fp16 fragments)
    prep_wf_kernel<<<(36864 + 255)/256, 256>>>(w1, w2);
    prep_of_kernel<<<(9216 + 255)/256, 256>>>(off1_w, mod1_w, off2_w, mod2_w);
    // 2) bn1 -> NHWC r1
    bn1_nhwc_kernel<<<8192, 256>>>(x, bn1_g, bn1_b, bn1_m, bn1_v);
    // 3) offsets + mask for layer 1
    offmod_mma_kernel<<<1024, 256, OFFMOD_SMEM>>>(r1p, of1, off1_b, mod1_b);
    // 4) deform conv 1 (+prelu) -> NHWC d1
    deform_mma_kernel<0><<<1024, 256, PIPE_SMEM>>>(r1p, wf1, alpha, nullptr, nullptr, nullptr, nullptr, d1p);
    // 5) offsets + mask for layer 2
    offmod_mma_kernel<<<1024, 256, OFFMOD_SMEM>>>(d1p, of2, off2_b, mod2_b);
    // 6) deform conv 2 (+bn2 +shortcut) -> CHW out
    deform_mma_kernel<1><<<1024, 256, PIPE_SMEM>>>(d1p, wf2, x, bn2_g, bn2_b, bn2_m, bn2_v, out);
}

// round 14
// speedup vs baseline: 8.4233x; 1.1240x over previous
#include <cuda_runtime.h>
#include <cuda_fp16.h>
#include <math.h>
#include <cstdint>

#define BSZ 4
#define CH  128
#define HH  128
#define WW  128
#define HWP (HH*WW)

typedef unsigned long long u64;
typedef uint32_t u32;

// ================= scratch (static device memory) =================
__device__ __half g_r1 [(size_t)BSZ*HWP*CH];  // bn1 output, NHWC fp16
__device__ __half g_d1 [(size_t)BSZ*HWP*CH];  // layer1 output, NHWC fp16
__device__ float g_offm[(size_t)BSZ*27*HWP];  // CHW planes: 0..17 offsets, 18..26 mask
// deform weights, fragment-packed fp16: [k][mi 8][ki 8][lane 32] uint4
__device__ uint4 g_wF1[9*8*8*32];
__device__ uint4 g_wF2[9*8*8*32];
// offmod weights (27 rows padded to 32): [k][mi 2][ki 8][lane 32] uint4
__device__ uint4 g_oF1[9*2*8*32];
__device__ uint4 g_oF2[9*2*8*32];

// ================= helpers =================
__device__ __forceinline__ u32 smem_to_u32(const void* p){
    u32 a; asm("{ .reg .u64 t; cvta.to.shared.u64 t, %1; cvt.u32.u64 %0, t; }" : "=r"(a) : "l"(p));
    return a;
}
__device__ __forceinline__ u32 pack_h2(float a, float b){
    __half2 h = __floats2half2_rn(a, b);
    return *(u32*)&h;
}
__device__ __forceinline__ void mma_f16(float* d, const u32* a, u32 b0, u32 b1){
    asm volatile(
        "mma.sync.aligned.m16n8k16.row.col.f32.f16.f16.f32 "
        "{%0,%1,%2,%3}, {%4,%5,%6,%7}, {%8,%9}, {%0,%1,%2,%3};"
        : "+f"(d[0]), "+f"(d[1]), "+f"(d[2]), "+f"(d[3])
        : "r"(a[0]), "r"(a[1]), "r"(a[2]), "r"(a[3]), "r"(b0), "r"(b1));
}
// non-trans: cols smem is px-major (already B^T) -> direct col-major B fragment
__device__ __forceinline__ void ldmx4(u32* r, u32 addr){
    asm volatile("ldmatrix.sync.aligned.m8n8.x4.shared.b16 {%0,%1,%2,%3}, [%4];"
        : "=r"(r[0]), "=r"(r[1]), "=r"(r[2]), "=r"(r[3]) : "r"(addr));
}

#define ROWB 272
#define BUFB (64*ROWB)        // 17408 bytes per cols buffer (fp16)
#define PIPE_SMEM (2*BUFB)    // 34816 bytes double-buffered (deform)

// offmod patch: [row 3][px 66][272B] fp16
#define OPX_STRIDE 272
#define OROW_STRIDE (66*OPX_STRIDE)      // 17952
#define OFFMOD_SMEM (3*OROW_STRIDE)      // 53856

// ================= prep: deform weights -> fragment order, fp16 ================
__global__ void prep_wf_kernel(const float* __restrict__ w1, const float* __restrict__ w2){
    int i = blockIdx.x*256 + threadIdx.x;
    if (i >= 36864) return;
    int lane = i & 31;
    int ki   = (i>>5) & 7;
    int mi   = (i>>8) & 7;
    int rest = i >> 11;            // 0..17
    int k    = rest % 9;
    int layer= rest / 9;
    const float* w = layer ? w2 : w1;

    int r  = lane >> 2;
    int cp = (lane & 3)*2;
    int row0 = mi*16 + r;
    int col0 = ki*16 + cp;

    float v[4][2];
#pragma unroll
    for (int q = 0; q < 4; q++){
        int ro = row0 + ((q & 1) ? 8 : 0);
        int co_ = col0 + ((q >> 1) ? 8 : 0);
#pragma unroll
        for (int e = 0; e < 2; e++)
            v[q][e] = w[(ro*CH + (co_+e))*9 + k];
    }
    uint4 o;
    o.x = pack_h2(v[0][0], v[0][1]);
    o.y = pack_h2(v[1][0], v[1][1]);
    o.z = pack_h2(v[2][0], v[2][1]);
    o.w = pack_h2(v[3][0], v[3][1]);
    uint4* dst = layer ? g_wF2 : g_wF1;
    dst[((k*8 + mi)*8 + ki)*32 + lane] = o;
}

// ================= prep: offmod weights (27 co pad 32) -> fragments ============
__global__ void prep_of_kernel(const float* __restrict__ o1w, const float* __restrict__ m1w,
                               const float* __restrict__ o2w, const float* __restrict__ m2w){
    int i = blockIdx.x*256 + threadIdx.x;
    if (i >= 9216) return;
    int lane = i & 31;
    int ki   = (i>>5) & 7;
    int mi   = (i>>8) & 1;
    int rest = i >> 9;             // 0..17
    int k    = rest % 9;
    int layer= rest / 9;
    const float* ow = layer ? o2w : o1w;
    const float* mw = layer ? m2w : m1w;

    int r  = lane >> 2;
    int cp = (lane & 3)*2;
    int row0 = mi*16 + r;
    int col0 = ki*16 + cp;

    float v[4][2];
#pragma unroll
    for (int q = 0; q < 4; q++){
        int ro = row0 + ((q & 1) ? 8 : 0);
        int c_ = col0 + ((q >> 1) ? 8 : 0);
#pragma unroll
        for (int e = 0; e < 2; e++){
            int c = c_ + e;
            float val = 0.f;
            if (ro < 18)      val = ow[(ro*CH + c)*9 + k];
            else if (ro < 27) val = mw[((ro-18)*CH + c)*9 + k];
            v[q][e] = val;
        }
    }
    uint4 o;
    o.x = pack_h2(v[0][0], v[0][1]);
    o.y = pack_h2(v[1][0], v[1][1]);
    o.z = pack_h2(v[2][0], v[2][1]);
    o.w = pack_h2(v[3][0], v[3][1]);
    uint4* dst = layer ? g_oF2 : g_oF1;
    dst[((k*2 + mi)*8 + ki)*32 + lane] = o;
}

// ================= bn1 + transpose to NHWC fp16 =================
__global__ void bn1_nhwc_kernel(const float* __restrict__ x,
                                const float* __restrict__ g, const float* __restrict__ b_,
                                const float* __restrict__ m, const float* __restrict__ v){
    __shared__ float tile[32][33];
    int bid = blockIdx.x;
    int wb = bid & 3, cb = (bid >> 2) & 3, h = (bid >> 4) & 127, b = bid >> 11;
    int tx = threadIdx.x & 31, ty = threadIdx.x >> 5;
    int c0 = cb*32, w0 = wb*32;
#pragma unroll
    for (int i = 0; i < 4; i++){
        int c = c0 + ty + i*8;
        float s  = g[c] * rsqrtf(v[c] + 1e-5f);
        float bb = b_[c] - m[c]*s;
        float xv = x[((size_t)(b*CH + c))*HWP + h*WW + w0 + tx];
        tile[ty + i*8][tx] = xv*s + bb;
    }
    __syncthreads();
#pragma unroll
    for (int i = 0; i < 4; i++){
        int w = w0 + ty + i*8;
        g_r1[(((size_t)b*HWP) + h*WW + w)*CH + c0 + tx] = __float2half(tile[tx][ty + i*8]);
    }
}

// ================= offmod via HMMA fp16, shared 3-row patch (fp16 src copy) =====
// grid 1024 = b*h*2half; block 256 (8 warps). M=32(27), N=64px, K=128/tap x 9 taps.
__global__ void __launch_bounds__(256,3)
offmod_mma_kernel(const __half* __restrict__ src, const uint4* __restrict__ oF,
                  const float* __restrict__ offb, const float* __restrict__ modb){
    extern __shared__ __align__(16) char dsm[];

    int t = threadIdx.x, lane = t & 31, wid = t >> 5;
    int b = blockIdx.x >> 8, rem = blockIdx.x & 255;
    int h = rem >> 1, w0 = (rem & 1) << 6;

    int mi  = wid >> 2;            // 0..1
    int px0 = (wid & 3) * 16;

    int sub  = lane & 7;
    int grp  = lane >> 3;
    int lrow = ((grp >> 1) << 3) + sub;
    int lcoff= (grp & 1) << 4;

    u32 smb = smem_to_u32(dsm);
    const __half* srcb = src + (size_t)b*HWP*CH;

    // ---- copy 3x66 fp16 patch once (no conversion needed) ----
    // slot i: pair = i>>4 (row*66+px), s16 = i&15 -> 8 channels (16B)
    for (int i = t; i < 198*16; i += 256){
        int pair = i >> 4;
        int s16  = i & 15;
        int row  = pair / 66;
        int px   = pair - row*66;
        int y = h - 1 + row;
        int x = w0 - 1 + px;
        bool ok = ((unsigned)y < HH) && ((unsigned)x < WW);
        uint4 val = make_uint4(0,0,0,0);
        if (ok) val = ((const uint4*)(srcb + ((size_t)y*WW + x)*CH))[s16];
        *(uint4*)(dsm + row*OROW_STRIDE + px*OPX_STRIDE + s16*16) = val;
    }
    __syncthreads();

    float acc[2][4];
#pragma unroll
    for (int n = 0; n < 2; n++)
#pragma unroll
        for (int e = 0; e < 4; e++) acc[n][e] = 0.f;

#pragma unroll
    for (int k = 0; k < 9; k++){
        int ky = k/3, kx = k - ky*3;
        u32 cHb = smb + ky*OROW_STRIDE + (px0 + lrow + kx)*OPX_STRIDE + lcoff;
        const uint4* wH = oF + (size_t)((k*2 + mi)*8)*32;
#pragma unroll
        for (int ki = 0; ki < 8; ki++){
            uint4 aH = wH[ki*32 + lane];
            u32 bh[4];
            ldmx4(bh, cHb + ki*32);
#pragma unroll
            for (int n = 0; n < 2; n++)
                mma_f16(acc[n], (const u32*)&aH, bh[2*n], bh[2*n+1]);
        }
    }

    // epilogue -> g_offm CHW planes
    int rfrag = lane >> 2;
    int cfrag = (lane & 3)*2;
    int coA = mi*16 + rfrag;
    int coB = coA + 8;
#pragma unroll
    for (int n = 0; n < 2; n++){
        int px = px0 + n*8 + cfrag;
        size_t pb = (size_t)h*WW + w0 + px;
#pragma unroll
        for (int half = 0; half < 2; half++){
            int co = half ? coB : coA;
            float d0 = half ? acc[n][2] : acc[n][0];
            float d1 = half ? acc[n][3] : acc[n][1];
            if (co < 18){
                float bb = offb[co];
                *(float2*)(g_offm + ((size_t)(b*27 + co))*HWP + pb) = make_float2(d0+bb, d1+bb);
            } else if (co < 27){
                float bb = modb[co-18];
                float a0 = 2.f/(1.f + __expf(-(d0 + bb)));
                float a1 = 2.f/(1.f + __expf(-(d1 + bb)));
                *(float2*)(g_offm + ((size_t)(b*27 + co))*HWP + pb) = make_float2(a0, a1);
            }
        }
    }
}

// ================= deformable conv via fp16 HMMA, fp16 NHWC gather =============
// grid 1024; block 256 (8 warps); tile 64px x 128co.
// MODE 0: out = prelu(conv) -> NHWC fp16 d1 (p0 = alpha)
// MODE 1: out = bn2(conv) + x -> CHW fp32 d_out (p0 = x CHW)
template<int MODE>
__global__ void __launch_bounds__(256,2)
deform_mma_kernel(const __half* __restrict__ src, const uint4* __restrict__ wF,
                  const float* __restrict__ p0,
                  const float* __restrict__ bn_g, const float* __restrict__ bn_b,
                  const float* __restrict__ bn_m, const float* __restrict__ bn_v,
                  void* __restrict__ out_){
    extern __shared__ __align__(16) char dsm[];

    int t = threadIdx.x, lane = t & 31, wid = t >> 5;
    int b = blockIdx.x >> 8, rem = blockIdx.x & 255;
    int h = rem >> 1, w0 = (rem & 1) << 6;

    int co0 = (wid >> 1)*32;
    int px0 = (wid & 1)*32;
    int miB = co0 >> 4;

    int sub  = lane & 7;
    int grp  = lane >> 3;
    int lrow = ((grp >> 1) << 3) + sub;
    int lcoff= (grp & 1) << 4;

    u32 smb = smem_to_u32(dsm);

    float acc[2][4][4];
#pragma unroll
    for (int m = 0; m < 2; m++)
#pragma unroll
        for (int n = 0; n < 4; n++)
#pragma unroll
            for (int e = 0; e < 4; e++) acc[m][n][e] = 0.f;

    const __half* srcb = src + (size_t)b*HWP*CH;
    const float*  offm = g_offm + (size_t)b*27*HWP;

    int   rad0=0, rad1=0, rad2=0, rad3=0;
    float rwt0=0.f, rwt1=0.f, rwt2=0.f, rwt3=0.f;

    auto corners = [&](int k){
        if (lane < 8){
            int w = w0 + wid + lane*8;
            int p = h*WW + w;
            float oy = offm[(2*k  )*HWP + p];
            float ox = offm[(2*k+1)*HWP + p];
            float mv = offm[(18+k )*HWP + p];
            int ky = k/3, kx = k - ky*3;
            float py  = (float)(h - 1 + ky) + oy;
            float pxf = (float)(w - 1 + kx) + ox;
            float y0f = floorf(py), x0f = floorf(pxf);
            float ay = py - y0f, ax = pxf - x0f;
            int y0 = (int)y0f, x0 = (int)x0f;
#pragma unroll
            for (int j = 0; j < 4; j++){
                int dy = j >> 1, dx = j & 1;
                int yi = y0 + dy, xi = x0 + dx;
                bool ok = ((unsigned)yi < HH) && ((unsigned)xi < WW);
                int yc = min(max(yi, 0), HH-1);
                int xc = min(max(xi, 0), WW-1);
                float wy = dy ? ay : 1.f - ay;
                float wx = dx ? ax : 1.f - ax;
                int   ad = (yc*WW + xc)*CH;
                float wt = ok ? wy*wx*mv : 0.f;
                if (j == 0){ rad0 = ad; rwt0 = wt; }
                else if (j == 1){ rad1 = ad; rwt1 = wt; }
                else if (j == 2){ rad2 = ad; rwt2 = wt; }
                else            { rad3 = ad; rwt3 = wt; }
            }
        }
    };

    auto blend4 = [&](uint2 r, float f, float4 &v){
        float2 a = __half22float2(*(__half2*)&r.x);
        float2 c = __half22float2(*(__half2*)&r.y);
        v.x += f*a.x; v.y += f*a.y; v.z += f*c.x; v.w += f*c.y;
    };

    auto gather = [&](int buf){
        char* cH = dsm + buf*BUFB;
#pragma unroll
        for (int it = 0; it < 8; it++){
            int a0 = __shfl_sync(0xffffffffu, rad0, it);
            int a1 = __shfl_sync(0xffffffffu, rad1, it);
            int a2 = __shfl_sync(0xffffffffu, rad2, it);
            int a3 = __shfl_sync(0xffffffffu, rad3, it);
            float f0 = __shfl_sync(0xffffffffu, rwt0, it);
            float f1 = __shfl_sync(0xffffffffu, rwt1, it);
            float f2 = __shfl_sync(0xffffffffu, rwt2, it);
            float f3 = __shfl_sync(0xffffffffu, rwt3, it);
            int px = wid + it*8;
            uint2 q0 = ((const uint2*)(srcb + a0))[lane];   // 4 fp16 channels
            uint2 q1 = ((const uint2*)(srcb + a1))[lane];
            uint2 q2 = ((const uint2*)(srcb + a2))[lane];
            uint2 q3 = ((const uint2*)(srcb + a3))[lane];
            float4 vv = make_float4(0.f,0.f,0.f,0.f);
            blend4(q0, f0, vv);
            blend4(q1, f1, vv);
            blend4(q2, f2, vv);
            blend4(q3, f3, vv);
            *(uint2*)(cH + px*ROWB + lane*8) =
                make_uint2(pack_h2(vv.x, vv.y), pack_h2(vv.z, vv.w));
        }
    };

    corners(0);
    gather(0);

    for (int k = 0; k < 9; k++){
        __syncthreads();                 // buf k&1 fully written; prev readers done
        if (k < 8) corners(k+1);
        u32 cHb = smb + (k & 1)*BUFB;
        const uint4* wH = wF + (size_t)(k*8)*8*32;
#pragma unroll
        for (int ki = 0; ki < 8; ki++){
            uint4 aH0 = wH[((miB  )*8 + ki)*32 + lane];
            uint4 aH1 = wH[((miB+1)*8 + ki)*32 + lane];
            u32 adr0 = (u32)((px0 + lrow)*ROWB + ki*32 + lcoff);
            u32 adr1 = adr0 + 16*ROWB;
            u32 bh[8];
            ldmx4(bh    , cHb + adr0);   // n-tiles 0,1
            ldmx4(bh + 4, cHb + adr1);   // n-tiles 2,3
#pragma unroll
            for (int n = 0; n < 4; n++){
                mma_f16(acc[0][n], (const u32*)&aH0, bh[2*n], bh[2*n+1]);
                mma_f16(acc[1][n], (const u32*)&aH1, bh[2*n], bh[2*n+1]);
            }
        }
        if (k < 8) gather((k+1) & 1);
    }

    // ================= epilogue =================
    int rfrag = lane >> 2;
    int cfrag = (lane & 3)*2;
#pragma unroll
    for (int m = 0; m < 2; m++){
        int coA = co0 + m*16 + rfrag;
        int coB = coA + 8;
        if (MODE == 0){
            __half* out = (__half*)out_;
            float aA = p0[coA], aB = p0[coB];
#pragma unroll
            for (int n = 0; n < 4; n++){
                int px = px0 + n*8 + cfrag;
                size_t base = (((size_t)b*HWP) + h*WW + w0 + px)*CH;   // NHWC
                float d0 = acc[m][n][0], d1 = acc[m][n][1];
                float d2 = acc[m][n][2], d3 = acc[m][n][3];
                out[base + coA]      = __float2half(d0 > 0.f ? d0 : aA*d0);
                out[base + CH + coA] = __float2half(d1 > 0.f ? d1 : aA*d1);
                out[base + coB]      = __float2half(d2 > 0.f ? d2 : aB*d2);
                out[base + CH + coB] = __float2half(d3 > 0.f ? d3 : aB*d3);
            }
        } else {
            float* out = (float*)out_;
            float sA  = bn_g[coA] * rsqrtf(bn_v[coA] + 1e-5f);
            float bA  = bn_b[coA] - bn_m[coA]*sA;
            float sB  = bn_g[coB] * rsqrtf(bn_v[coB] + 1e-5f);
            float bB  = bn_b[coB] - bn_m[coB]*sB;
#pragma unroll
            for (int n = 0; n < 4; n++){
                int px = px0 + n*8 + cfrag;
                size_t baseA = ((size_t)(b*CH + coA))*HWP + (size_t)h*WW + w0 + px;
                size_t baseB = baseA + (size_t)8*HWP;
                float2 xA = *(const float2*)(p0 + baseA);
                float2 xB = *(const float2*)(p0 + baseB);
                float d0 = acc[m][n][0], d1 = acc[m][n][1];
                float d2 = acc[m][n][2], d3 = acc[m][n][3];
                *(float2*)(out + baseA) = make_float2(d0*sA + bA + xA.x, d1*sA + bA + xA.y);
                *(float2*)(out + baseB) = make_float2(d2*sB + bB + xB.x, d3*sB + bB + xB.y);
            }
        }
    }
}

// ================= host launcher =================
extern "C" void kernel_launch(void* const* d_in, const int* in_sizes, int n_in,
                              void* d_out, int out_size){
    const float* x      = (const float*)d_in[0];
    const float* bn1_g  = (const float*)d_in[1];
    const float* bn1_b  = (const float*)d_in[2];
    const float* bn1_m  = (const float*)d_in[3];
    const float* bn1_v  = (const float*)d_in[4];
    const float* off1_w = (const float*)d_in[5];
    const float* off1_b = (const float*)d_in[6];
    const float* mod1_w = (const float*)d_in[7];
    const float* mod1_b = (const float*)d_in[8];
    const float* w1     = (const float*)d_in[9];
    const float* alpha  = (const float*)d_in[10];
    const float* off2_w = (const float*)d_in[11];
    const float* off2_b = (const float*)d_in[12];
    const float* mod2_w = (const float*)d_in[13];
    const float* mod2_b = (const float*)d_in[14];
    const float* w2     = (const float*)d_in[15];
    const float* bn2_g  = (const float*)d_in[16];
    const float* bn2_b  = (const float*)d_in[17];
    const float* bn2_m  = (const float*)d_in[18];
    const float* bn2_v  = (const float*)d_in[19];
    float* out = (float*)d_out;

    __half *r1p, *d1p;
    uint4 *wf1, *wf2, *of1, *of2;
    cudaGetSymbolAddress((void**)&r1p, g_r1);
    cudaGetSymbolAddress((void**)&d1p, g_d1);
    cudaGetSymbolAddress((void**)&wf1, g_wF1);
    cudaGetSymbolAddress((void**)&wf2, g_wF2);
    cudaGetSymbolAddress((void**)&of1, g_oF1);
    cudaGetSymbolAddress((void**)&of2, g_oF2);

    cudaFuncSetAttribute(offmod_mma_kernel,    cudaFuncAttributeMaxDynamicSharedMemorySize, OFFMOD_SMEM);
    cudaFuncSetAttribute(deform_mma_kernel<0>, cudaFuncAttributeMaxDynamicSharedMemorySize, PIPE_SMEM);
    cudaFuncSetAttribute(deform_mma_kernel<1>, cudaFuncAttributeMaxDynamicSharedMemorySize, PIPE_SMEM);

    // 1) weight prep (fp16 fragments)
    prep_wf_kernel<<<(36864 + 255)/256, 256>>>(w1, w2);
    prep_of_kernel<<<(9216 + 255)/256, 256>>>(off1_w, mod1_w, off2_w, mod2_w);
    // 2) bn1 -> NHWC fp16 r1
    bn1_nhwc_kernel<<<8192, 256>>>(x, bn1_g, bn1_b, bn1_m, bn1_v);
    // 3) offsets + mask for layer 1
    offmod_mma_kernel<<<1024, 256, OFFMOD_SMEM>>>(r1p, of1, off1_b, mod1_b);
    // 4) deform conv 1 (+prelu) -> NHWC fp16 d1
    deform_mma_kernel<0><<<1024, 256, PIPE_SMEM>>>(r1p, wf1, alpha, nullptr, nullptr, nullptr, nullptr, d1p);
    // 5) offsets + mask for layer 2
    offmod_mma_kernel<<<1024, 256, OFFMOD_SMEM>>>(d1p, of2, off2_b, mod2_b);
    // 6) deform conv 2 (+bn2 +shortcut) -> CHW fp32 out
    deform_mma_kernel<1><<<1024, 256, PIPE_SMEM>>>(d1p, wf2, x, bn2_g, bn2_b, bn2_m, bn2_v, out);
}

// round 15
// speedup vs baseline: 9.0349x; 1.0726x over previous
#include <cuda_runtime.h>
#include <cuda_fp16.h>
#include <math.h>
#include <cstdint>

#define BSZ 4
#define CH  128
#define HH  128
#define WW  128
#define HWP (HH*WW)

typedef unsigned long long u64;
typedef uint32_t u32;

// ================= scratch (static device memory) =================
__device__ __half g_r1 [(size_t)BSZ*HWP*CH];  // bn1 output, NHWC fp16
__device__ __half g_d1 [(size_t)BSZ*HWP*CH];  // layer1 output, NHWC fp16
// deform weights, fragment-packed fp16: [k][mi 8][ki 8][lane 32] uint4
__device__ uint4 g_wF1[9*8*8*32];
__device__ uint4 g_wF2[9*8*8*32];
// offmod weights (27 rows padded to 32): [k][mi 2][ki 8][lane 32] uint4
__device__ uint4 g_oF1[9*2*8*32];
__device__ uint4 g_oF2[9*2*8*32];

// ================= helpers =================
__device__ __forceinline__ u32 smem_to_u32(const void* p){
    u32 a; asm("{ .reg .u64 t; cvta.to.shared.u64 t, %1; cvt.u32.u64 %0, t; }" : "=r"(a) : "l"(p));
    return a;
}
__device__ __forceinline__ u32 pack_h2(float a, float b){
    __half2 h = __floats2half2_rn(a, b);
    return *(u32*)&h;
}
__device__ __forceinline__ void mma_f16(float* d, const u32* a, u32 b0, u32 b1){
    asm volatile(
        "mma.sync.aligned.m16n8k16.row.col.f32.f16.f16.f32 "
        "{%0,%1,%2,%3}, {%4,%5,%6,%7}, {%8,%9}, {%0,%1,%2,%3};"
        : "+f"(d[0]), "+f"(d[1]), "+f"(d[2]), "+f"(d[3])
        : "r"(a[0]), "r"(a[1]), "r"(a[2]), "r"(a[3]), "r"(b0), "r"(b1));
}
// non-trans: cols smem is px-major (already B^T) -> direct col-major B fragment
__device__ __forceinline__ void ldmx4(u32* r, u32 addr){
    asm volatile("ldmatrix.sync.aligned.m8n8.x4.shared.b16 {%0,%1,%2,%3}, [%4];"
        : "=r"(r[0]), "=r"(r[1]), "=r"(r[2]), "=r"(r[3]) : "r"(addr));
}

#define ROWB 272
#define BUFB (64*ROWB)        // 17408 bytes per cols buffer (fp16)

// phase-A patch: [row 3][px 66][272B] fp16
#define OPX_STRIDE 272
#define OROW_STRIDE (66*OPX_STRIDE)      // 17952
#define OPATCH_BYTES (3*OROW_STRIDE)     // 53856
// s_offm lives above the union of (patch, cols double buffer)
#define SOFFM_OFF 53856                   // 27*64 floats = 6912 B
#define FUSED_SMEM (SOFFM_OFF + 6912)     // 60768

// ================= prep: all weights -> fragment order, fp16 ================
// i < 36864: deform weights [layer][k][mi 8][ki 8][lane]
// else     : offmod weights [layer][k][mi 2][ki 8][lane]
__global__ void prep_all_kernel(const float* __restrict__ w1, const float* __restrict__ w2,
                                const float* __restrict__ o1w, const float* __restrict__ m1w,
                                const float* __restrict__ o2w, const float* __restrict__ m2w){
    int i = blockIdx.x*256 + threadIdx.x;
    if (i < 36864){
        int lane = i & 31;
        int ki   = (i>>5) & 7;
        int mi   = (i>>8) & 7;
        int rest = i >> 11;            // 0..17
        int k    = rest % 9;
        int layer= rest / 9;
        const float* w = layer ? w2 : w1;
        int r  = lane >> 2;
        int cp = (lane & 3)*2;
        int row0 = mi*16 + r;
        int col0 = ki*16 + cp;
        float v[4][2];
#pragma unroll
        for (int q = 0; q < 4; q++){
            int ro = row0 + ((q & 1) ? 8 : 0);
            int co_ = col0 + ((q >> 1) ? 8 : 0);
#pragma unroll
            for (int e = 0; e < 2; e++)
                v[q][e] = w[(ro*CH + (co_+e))*9 + k];
        }
        uint4 o;
        o.x = pack_h2(v[0][0], v[0][1]);
        o.y = pack_h2(v[1][0], v[1][1]);
        o.z = pack_h2(v[2][0], v[2][1]);
        o.w = pack_h2(v[3][0], v[3][1]);
        uint4* dst = layer ? g_wF2 : g_wF1;
        dst[((k*8 + mi)*8 + ki)*32 + lane] = o;
    } else if (i < 36864 + 9216){
        int j = i - 36864;
        int lane = j & 31;
        int ki   = (j>>5) & 7;
        int mi   = (j>>8) & 1;
        int rest = j >> 9;             // 0..17
        int k    = rest % 9;
        int layer= rest / 9;
        const float* ow = layer ? o2w : o1w;
        const float* mw = layer ? m2w : m1w;
        int r  = lane >> 2;
        int cp = (lane & 3)*2;
        int row0 = mi*16 + r;
        int col0 = ki*16 + cp;
        float v[4][2];
#pragma unroll
        for (int q = 0; q < 4; q++){
            int ro = row0 + ((q & 1) ? 8 : 0);
            int c_ = col0 + ((q >> 1) ? 8 : 0);
#pragma unroll
            for (int e = 0; e < 2; e++){
                int c = c_ + e;
                float val = 0.f;
                if (ro < 18)      val = ow[(ro*CH + c)*9 + k];
                else if (ro < 27) val = mw[((ro-18)*CH + c)*9 + k];
                v[q][e] = val;
            }
        }
        uint4 o;
        o.x = pack_h2(v[0][0], v[0][1]);
        o.y = pack_h2(v[1][0], v[1][1]);
        o.z = pack_h2(v[2][0], v[2][1]);
        o.w = pack_h2(v[3][0], v[3][1]);
        uint4* dst = layer ? g_oF2 : g_oF1;
        dst[((k*2 + mi)*8 + ki)*32 + lane] = o;
    }
}

// ================= bn1 + transpose to NHWC fp16 =================
__global__ void bn1_nhwc_kernel(const float* __restrict__ x,
                                const float* __restrict__ g, const float* __restrict__ b_,
                                const float* __restrict__ m, const float* __restrict__ v){
    __shared__ float tile[32][33];
    int bid = blockIdx.x;
    int wb = bid & 3, cb = (bid >> 2) & 3, h = (bid >> 4) & 127, b = bid >> 11;
    int tx = threadIdx.x & 31, ty = threadIdx.x >> 5;
    int c0 = cb*32, w0 = wb*32;
#pragma unroll
    for (int i = 0; i < 4; i++){
        int c = c0 + ty + i*8;
        float s  = g[c] * rsqrtf(v[c] + 1e-5f);
        float bb = b_[c] - m[c]*s;
        float xv = x[((size_t)(b*CH + c))*HWP + h*WW + w0 + tx];
        tile[ty + i*8][tx] = xv*s + bb;
    }
    __syncthreads();
#pragma unroll
    for (int i = 0; i < 4; i++){
        int w = w0 + ty + i*8;
        g_r1[(((size_t)b*HWP) + h*WW + w)*CH + c0 + tx] = __float2half(tile[tx][ty + i*8]);
    }
}

// ================= fused offmod + deformable conv =================
// grid 1024 = b*h*2half; block 256 (8 warps); tile 64px x 128co.
// Phase A: dense 3x3 conv (27 ch) on the 3x66 patch -> s_offm[27][64] in smem.
// Phase B: deformable conv, corners from s_offm.
// MODE 0: out = prelu(conv) -> NHWC fp16 d1 (p0 = alpha)
// MODE 1: out = bn2(conv) + x -> CHW fp32 d_out (p0 = x CHW)
template<int MODE>
__global__ void __launch_bounds__(256,2)
fused_layer_kernel(const __half* __restrict__ src,
                   const uint4* __restrict__ oF,
                   const float* __restrict__ offb, const float* __restrict__ modb,
                   const uint4* __restrict__ wF,
                   const float* __restrict__ p0,
                   const float* __restrict__ bn_g, const float* __restrict__ bn_b,
                   const float* __restrict__ bn_m, const float* __restrict__ bn_v,
                   void* __restrict__ out_){
    extern __shared__ __align__(16) char dsm[];
    float* s_offm = (float*)(dsm + SOFFM_OFF);   // [27][64]

    int t = threadIdx.x, lane = t & 31, wid = t >> 5;
    int b = blockIdx.x >> 8, rem = blockIdx.x & 255;
    int h = rem >> 1, w0 = (rem & 1) << 6;

    int sub  = lane & 7;
    int grp  = lane >> 3;
    int lrow = ((grp >> 1) << 3) + sub;
    int lcoff= (grp & 1) << 4;
    int rfrag = lane >> 2;
    int cfrag = (lane & 3)*2;

    u32 smb = smem_to_u32(dsm);
    const __half* srcb = src + (size_t)b*HWP*CH;

    // ================= PHASE A: offset/mask conv =================
    {
        // copy 3x66 fp16 patch
        for (int i = t; i < 198*16; i += 256){
            int pair = i >> 4;
            int s16  = i & 15;
            int row  = pair / 66;
            int px   = pair - row*66;
            int y = h - 1 + row;
            int x = w0 - 1 + px;
            bool ok = ((unsigned)y < HH) && ((unsigned)x < WW);
            uint4 val = make_uint4(0,0,0,0);
            if (ok) val = ((const uint4*)(srcb + ((size_t)y*WW + x)*CH))[s16];
            *(uint4*)(dsm + row*OROW_STRIDE + px*OPX_STRIDE + s16*16) = val;
        }
        __syncthreads();

        int miA  = wid >> 2;            // 0..1
        int px0A = (wid & 3) * 16;

        float accA[2][4];
#pragma unroll
        for (int n = 0; n < 2; n++)
#pragma unroll
            for (int e = 0; e < 4; e++) accA[n][e] = 0.f;

#pragma unroll
        for (int k = 0; k < 9; k++){
            int ky = k/3, kx = k - ky*3;
            u32 cHb = smb + ky*OROW_STRIDE + (px0A + lrow + kx)*OPX_STRIDE + lcoff;
            const uint4* wH = oF + (size_t)((k*2 + miA)*8)*32;
#pragma unroll
            for (int ki = 0; ki < 8; ki++){
                uint4 aH = wH[ki*32 + lane];
                u32 bh[4];
                ldmx4(bh, cHb + ki*32);
#pragma unroll
                for (int n = 0; n < 2; n++)
                    mma_f16(accA[n], (const u32*)&aH, bh[2*n], bh[2*n+1]);
            }
        }

        // epilogue -> s_offm[27][64]
        int coA = miA*16 + rfrag;
        int coB = coA + 8;
#pragma unroll
        for (int n = 0; n < 2; n++){
            int px = px0A + n*8 + cfrag;
#pragma unroll
            for (int half = 0; half < 2; half++){
                int co = half ? coB : coA;
                float d0 = half ? accA[n][2] : accA[n][0];
                float d1 = half ? accA[n][3] : accA[n][1];
                if (co < 18){
                    float bb = offb[co];
                    s_offm[co*64 + px]     = d0 + bb;
                    s_offm[co*64 + px + 1] = d1 + bb;
                } else if (co < 27){
                    float bb = modb[co-18];
                    s_offm[co*64 + px]     = 2.f/(1.f + __expf(-(d0 + bb)));
                    s_offm[co*64 + px + 1] = 2.f/(1.f + __expf(-(d1 + bb)));
                }
            }
        }
    }
    __syncthreads();   // patch reads done + s_offm complete; cols may overwrite patch

    // ================= PHASE B: deformable conv =================
    int co0 = (wid >> 1)*32;
    int px0 = (wid & 1)*32;
    int miB = co0 >> 4;

    float acc[2][4][4];
#pragma unroll
    for (int m = 0; m < 2; m++)
#pragma unroll
        for (int n = 0; n < 4; n++)
#pragma unroll
            for (int e = 0; e < 4; e++) acc[m][n][e] = 0.f;

    int   rad0=0, rad1=0, rad2=0, rad3=0;
    float rwt0=0.f, rwt1=0.f, rwt2=0.f, rwt3=0.f;

    auto corners = [&](int k){
        if (lane < 8){
            int pw = wid + lane*8;          // pixel index in tile
            int w  = w0 + pw;
            float oy = s_offm[(2*k  )*64 + pw];
            float ox = s_offm[(2*k+1)*64 + pw];
            float mv = s_offm[(18+k )*64 + pw];
            int ky = k/3, kx = k - ky*3;
            float py  = (float)(h - 1 + ky) + oy;
            float pxf = (float)(w - 1 + kx) + ox;
            float y0f = floorf(py), x0f = floorf(pxf);
            float ay = py - y0f, ax = pxf - x0f;
            int y0 = (int)y0f, x0 = (int)x0f;
#pragma unroll
            for (int j = 0; j < 4; j++){
                int dy = j >> 1, dx = j & 1;
                int yi = y0 + dy, xi = x0 + dx;
                bool ok = ((unsigned)yi < HH) && ((unsigned)xi < WW);
                int yc = min(max(yi, 0), HH-1);
                int xc = min(max(xi, 0), WW-1);
                float wy = dy ? ay : 1.f - ay;
                float wx = dx ? ax : 1.f - ax;
                int   ad = (yc*WW + xc)*CH;
                float wt = ok ? wy*wx*mv : 0.f;
                if (j == 0){ rad0 = ad; rwt0 = wt; }
                else if (j == 1){ rad1 = ad; rwt1 = wt; }
                else if (j == 2){ rad2 = ad; rwt2 = wt; }
                else            { rad3 = ad; rwt3 = wt; }
            }
        }
    };

    auto blend4 = [&](uint2 r, float f, float4 &v){
        float2 a = __half22float2(*(__half2*)&r.x);
        float2 c = __half22float2(*(__half2*)&r.y);
        v.x += f*a.x; v.y += f*a.y; v.z += f*c.x; v.w += f*c.y;
    };

    auto gather = [&](int buf){
        char* cH = dsm + buf*BUFB;
#pragma unroll
        for (int it = 0; it < 8; it++){
            int a0 = __shfl_sync(0xffffffffu, rad0, it);
            int a1 = __shfl_sync(0xffffffffu, rad1, it);
            int a2 = __shfl_sync(0xffffffffu, rad2, it);
            int a3 = __shfl_sync(0xffffffffu, rad3, it);
            float f0 = __shfl_sync(0xffffffffu, rwt0, it);
            float f1 = __shfl_sync(0xffffffffu, rwt1, it);
            float f2 = __shfl_sync(0xffffffffu, rwt2, it);
            float f3 = __shfl_sync(0xffffffffu, rwt3, it);
            int px = wid + it*8;
            uint2 q0 = ((const uint2*)(srcb + a0))[lane];   // 4 fp16 channels
            uint2 q1 = ((const uint2*)(srcb + a1))[lane];
            uint2 q2 = ((const uint2*)(srcb + a2))[lane];
            uint2 q3 = ((const uint2*)(srcb + a3))[lane];
            float4 vv = make_float4(0.f,0.f,0.f,0.f);
            blend4(q0, f0, vv);
            blend4(q1, f1, vv);
            blend4(q2, f2, vv);
            blend4(q3, f3, vv);
            *(uint2*)(cH + px*ROWB + lane*8) =
                make_uint2(pack_h2(vv.x, vv.y), pack_h2(vv.z, vv.w));
        }
    };

    corners(0);
    gather(0);

    for (int k = 0; k < 9; k++){
        __syncthreads();                 // buf k&1 fully written; prev readers done
        if (k < 8) corners(k+1);
        u32 cHb = smb + (k & 1)*BUFB;
        const uint4* wH = wF + (size_t)(k*8)*8*32;
#pragma unroll
        for (int ki = 0; ki < 8; ki++){
            uint4 aH0 = wH[((miB  )*8 + ki)*32 + lane];
            uint4 aH1 = wH[((miB+1)*8 + ki)*32 + lane];
            u32 adr0 = (u32)((px0 + lrow)*ROWB + ki*32 + lcoff);
            u32 adr1 = adr0 + 16*ROWB;
            u32 bh[8];
            ldmx4(bh    , cHb + adr0);   // n-tiles 0,1
            ldmx4(bh + 4, cHb + adr1);   // n-tiles 2,3
#pragma unroll
            for (int n = 0; n < 4; n++){
                mma_f16(acc[0][n], (const u32*)&aH0, bh[2*n], bh[2*n+1]);
                mma_f16(acc[1][n], (const u32*)&aH1, bh[2*n], bh[2*n+1]);
            }
        }
        if (k < 8) gather((k+1) & 1);
    }

    // ================= epilogue =================
#pragma unroll
    for (int m = 0; m < 2; m++){
        int coA = co0 + m*16 + rfrag;
        int coB = coA + 8;
        if (MODE == 0){
            __half* out = (__half*)out_;
            float aA = p0[coA], aB = p0[coB];
#pragma unroll
            for (int n = 0; n < 4; n++){
                int px = px0 + n*8 + cfrag;
                size_t base = (((size_t)b*HWP) + h*WW + w0 + px)*CH;   // NHWC
                float d0 = acc[m][n][0], d1 = acc[m][n][1];
                float d2 = acc[m][n][2], d3 = acc[m][n][3];
                out[base + coA]      = __float2half(d0 > 0.f ? d0 : aA*d0);
                out[base + CH + coA] = __float2half(d1 > 0.f ? d1 : aA*d1);
                out[base + coB]      = __float2half(d2 > 0.f ? d2 : aB*d2);
                out[base + CH + coB] = __float2half(d3 > 0.f ? d3 : aB*d3);
            }
        } else {
            float* out = (float*)out_;
            float sA  = bn_g[coA] * rsqrtf(bn_v[coA] + 1e-5f);
            float bA  = bn_b[coA] - bn_m[coA]*sA;
            float sB  = bn_g[coB] * rsqrtf(bn_v[coB] + 1e-5f);
            float bB  = bn_b[coB] - bn_m[coB]*sB;
#pragma unroll
            for (int n = 0; n < 4; n++){
                int px = px0 + n*8 + cfrag;
                size_t baseA = ((size_t)(b*CH + coA))*HWP + (size_t)h*WW + w0 + px;
                size_t baseB = baseA + (size_t)8*HWP;
                float2 xA = *(const float2*)(p0 + baseA);
                float2 xB = *(const float2*)(p0 + baseB);
                float d0 = acc[m][n][0], d1 = acc[m][n][1];
                float d2 = acc[m][n][2], d3 = acc[m][n][3];
                *(float2*)(out + baseA) = make_float2(d0*sA + bA + xA.x, d1*sA + bA + xA.y);
                *(float2*)(out + baseB) = make_float2(d2*sB + bB + xB.x, d3*sB + bB + xB.y);
            }
        }
    }
}

// ================= host launcher =================
extern "C" void kernel_launch(void* const* d_in, const int* in_sizes, int n_in,
                              void* d_out, int out_size){
    const float* x      = (const float*)d_in[0];
    const float* bn1_g  = (const float*)d_in[1];
    const float* bn1_b  = (const float*)d_in[2];
    const float* bn1_m  = (const float*)d_in[3];
    const float* bn1_v  = (const float*)d_in[4];
    const float* off1_w = (const float*)d_in[5];
    const float* off1_b = (const float*)d_in[6];
    const float* mod1_w = (const float*)d_in[7];
    const float* mod1_b = (const float*)d_in[8];
    const float* w1     = (const float*)d_in[9];
    const float* alpha  = (const float*)d_in[10];
    const float* off2_w = (const float*)d_in[11];
    const float* off2_b = (const float*)d_in[12];
    const float* mod2_w = (const float*)d_in[13];
    const float* mod2_b = (const float*)d_in[14];
    const float* w2     = (const float*)d_in[15];
    const float* bn2_g  = (const float*)d_in[16];
    const float* bn2_b  = (const float*)d_in[17];
    const float* bn2_m  = (const float*)d_in[18];
    const float* bn2_v  = (const float*)d_in[19];
    float* out = (float*)d_out;

    __half *r1p, *d1p;
    uint4 *wf1, *wf2, *of1, *of2;
    cudaGetSymbolAddress((void**)&r1p, g_r1);
    cudaGetSymbolAddress((void**)&d1p, g_d1);
    cudaGetSymbolAddress((void**)&wf1, g_wF1);
    cudaGetSymbolAddress((void**)&wf2, g_wF2);
    cudaGetSymbolAddress((void**)&of1, g_oF1);
    cudaGetSymbolAddress((void**)&of2, g_oF2);

    cudaFuncSetAttribute(fused_layer_kernel<0>, cudaFuncAttributeMaxDynamicSharedMemorySize, FUSED_SMEM);
    cudaFuncSetAttribute(fused_layer_kernel<1>, cudaFuncAttributeMaxDynamicSharedMemorySize, FUSED_SMEM);

    // 1) weight prep (all fragments, one launch)
    prep_all_kernel<<<(36864 + 9216 + 255)/256, 256>>>(w1, w2, off1_w, mod1_w, off2_w, mod2_w);
    // 2) bn1 -> NHWC fp16 r1
    bn1_nhwc_kernel<<<8192, 256>>>(x, bn1_g, bn1_b, bn1_m, bn1_v);
    // 3) fused layer 1: offmod + deform (+prelu) -> NHWC fp16 d1
    fused_layer_kernel<0><<<1024, 256, FUSED_SMEM>>>(r1p, of1, off1_b, mod1_b, wf1, alpha,
                                                     nullptr, nullptr, nullptr, nullptr, d1p);
    // 4) fused layer 2: offmod + deform (+bn2 +shortcut) -> CHW fp32 out
    fused_layer_kernel<1><<<1024, 256, FUSED_SMEM>>>(d1p, of2, off2_b, mod2_b, wf2, x,
                                                     bn2_g, bn2_b, bn2_m, bn2_v, out);
}